// round 13
// baseline (speedup 1.0000x reference)
#include <cuda_runtime.h>
#include <cuda_bf16.h>
#include <math.h>
#include <stdint.h>

// ---------------- problem constants ----------------
static constexpr int TOK   = 4096;
static constexpr int DD    = 768;
static constexpr int HH    = 1536;
static constexpr int EE    = 64;
static constexpr int TOPK  = 6;
static constexpr int CAP   = 1536;
static constexpr int NPAIR = TOK * TOPK;        // 24576
static constexpr int OUT_MAIN = TOK * DD;

#define FULLMASK 0xFFFFFFFFu

// ---------------- scratch (static device memory) ----------------
__device__ float g_logits[TOK * EE];
__device__ float g_prob_sum[EE];
__device__ int   g_counts[EE];
__device__ int   g_tok[EE * CAP];
__device__ int   g_pairidx[EE * CAP];
__device__ float g_score[EE * CAP];
__device__ int   g_ident[TOK];
__device__ float g_ones[TOK];
// hi/lo bf16 split buffers
__device__ __nv_bfloat16 g_x_hi[(size_t)TOK * DD];
__device__ __nv_bfloat16 g_x_lo[(size_t)TOK * DD];
__device__ __nv_bfloat16 g_s1w_hi[(size_t)HH * DD];
__device__ __nv_bfloat16 g_s1w_lo[(size_t)HH * DD];
__device__ __nv_bfloat16 g_s2w_hi[(size_t)DD * HH];
__device__ __nv_bfloat16 g_s2w_lo[(size_t)DD * HH];
__device__ __nv_bfloat16 g_e1w_hi[(size_t)EE * HH * DD];
__device__ __nv_bfloat16 g_e1w_lo[(size_t)EE * HH * DD];
__device__ __nv_bfloat16 g_e2w_hi[(size_t)EE * DD * HH];
__device__ __nv_bfloat16 g_e2w_lo[(size_t)EE * DD * HH];
__device__ __nv_bfloat16 g_shh_hi[(size_t)TOK * HH];
__device__ __nv_bfloat16 g_shh_lo[(size_t)TOK * HH];
__device__ __nv_bfloat16 g_h_hi[(size_t)NPAIR * HH];
__device__ __nv_bfloat16 g_h_lo[(size_t)NPAIR * HH];

// segment sizes (in 8-float units)
static constexpr int XS_N8 = TOK * DD / 8;
static constexpr int S1_N8 = HH * DD / 8;
static constexpr int S2_N8 = DD * HH / 8;
static constexpr int E1_N8 = EE * HH * DD / 8;
static constexpr int E2_N8 = EE * DD * HH / 8;

// ---------------- helpers ----------------
__device__ __forceinline__ uint32_t smem_u32(const void* p) {
    uint32_t a;
    asm("{ .reg .u64 t; cvta.to.shared.u64 t, %1; cvt.u32.u64 %0, t; }" : "=r"(a) : "l"(p));
    return a;
}
__device__ __forceinline__ uint32_t cvt_bf2(float hi_upper, float lo_lower) {
    uint32_t r;
    asm("cvt.rn.bf16x2.f32 %0, %1, %2;" : "=r"(r) : "f"(hi_upper), "f"(lo_lower));
    return r;
}
__device__ __forceinline__ void split2(float v0, float v1, uint32_t& h, uint32_t& l) {
    h = cvt_bf2(v1, v0);
    float f0 = __uint_as_float(h << 16);
    float f1 = __uint_as_float(h & 0xffff0000u);
    l = cvt_bf2(v1 - f1, v0 - f0);
}
// 4 elements per thread: 8 independent LDG.128 in flight, then convert+store.
__device__ __forceinline__ void split_four(const float* __restrict__ src,
                                           __nv_bfloat16* __restrict__ hi,
                                           __nv_bfloat16* __restrict__ lo, int base) {
    float4 v[8];
#pragma unroll
    for (int j = 0; j < 4; j++) {
        const float4* s = (const float4*)src + (size_t)(base + j * 256) * 2;
        v[2 * j]     = s[0];
        v[2 * j + 1] = s[1];
    }
#pragma unroll
    for (int j = 0; j < 4; j++) {
        uint32_t h0, l0, h1, l1, h2, l2, h3, l3;
        split2(v[2 * j].x,     v[2 * j].y,     h0, l0);
        split2(v[2 * j].z,     v[2 * j].w,     h1, l1);
        split2(v[2 * j + 1].x, v[2 * j + 1].y, h2, l2);
        split2(v[2 * j + 1].z, v[2 * j + 1].w, h3, l3);
        ((uint4*)hi)[base + j * 256] = make_uint4(h0, h1, h2, h3);
        ((uint4*)lo)[base + j * 256] = make_uint4(l0, l1, l2, l3);
    }
}
__device__ __forceinline__ float gelu_ex(float x) {
    return 0.5f * x * (1.0f + erff(x * 0.70710678118654752f));
}
__device__ __forceinline__ void hmma(float* c, const uint32_t* a, uint32_t b0, uint32_t b1) {
    asm volatile(
        "mma.sync.aligned.m16n8k16.row.col.f32.bf16.bf16.f32 "
        "{%0,%1,%2,%3}, {%4,%5,%6,%7}, {%8,%9}, {%0,%1,%2,%3};"
        : "+f"(c[0]), "+f"(c[1]), "+f"(c[2]), "+f"(c[3])
        : "r"(a[0]), "r"(a[1]), "r"(a[2]), "r"(a[3]), "r"(b0), "r"(b1));
}
#define LDSM4(r, a) \
    asm volatile("ldmatrix.sync.aligned.m8n8.x4.shared.b16 {%0,%1,%2,%3}, [%4];" \
                 : "=r"((r)[0]), "=r"((r)[1]), "=r"((r)[2]), "=r"((r)[3]) : "r"(a))
__device__ __forceinline__ void cpa16(uint32_t dst, const void* src, uint32_t srcsz) {
    asm volatile("cp.async.cg.shared.global [%0], [%1], 16, %2;"
                 :: "r"(dst), "l"(src), "r"(srcsz));
}
#define CP_COMMIT() asm volatile("cp.async.commit_group;" ::: "memory")
#define CP_WAIT1()  asm volatile("cp.async.wait_group 1;" ::: "memory")

__device__ __forceinline__ unsigned long long ffma2(unsigned long long a,
                                                    unsigned long long b,
                                                    unsigned long long c) {
    unsigned long long d;
    asm("fma.rn.f32x2 %0, %1, %2, %3;" : "=l"(d) : "l"(a), "l"(b), "l"(c));
    return d;
}
__device__ __forceinline__ unsigned long long pack2f(float x) {
    unsigned long long d;
    asm("mov.b64 %0, {%1, %1};" : "=l"(d) : "f"(x));
    return d;
}
__device__ __forceinline__ float2 unpack2f(unsigned long long v) {
    float2 r;
    asm("mov.b64 {%0, %1}, %2;" : "=f"(r.x), "=f"(r.y) : "l"(v));
    return r;
}

// ---------------- fused prep: gate GEMM + ALL splits (4x ILP) + zero-out + reset ----------------
static constexpr int GATE_BLKS = 64;
static constexpr int XS_B = XS_N8 / 1024;           // 384
static constexpr int E1_B = E1_N8 / 1024;           // 9216
static constexpr int S1_B = S1_N8 / 1024;           // 144
static constexpr int E2_B = E2_N8 / 1024;           // 9216
static constexpr int S2_B = S2_N8 / 1024;           // 144
static constexpr int ZO_B = (TOK * DD / 4) / 1024;  // 768 (4 float4 per thread)
static constexpr int RS_B = TOK / 256;              // 16
static constexpr int PREP_BLKS =
    GATE_BLKS + XS_B + E1_B + S1_B + E2_B + S2_B + ZO_B + RS_B;

__global__ __launch_bounds__(256) void prep_kernel(
    const float* __restrict__ x, const float* __restrict__ gate_w,
    const float* __restrict__ e1_w, const float* __restrict__ sh1_w,
    const float* __restrict__ e2_w, const float* __restrict__ sh2_w,
    float* __restrict__ out) {
    int bx = blockIdx.x;
    int tid = threadIdx.x;
    if (bx < GATE_BLKS) {
        constexpr int BM = 64, BN = 64, BK = 16, TM = 4, TN = 4;
        __shared__ __align__(16) float As[BK][BM + 4];
        __shared__ __align__(16) float Bs[BK][BN + 4];
        int m0 = bx * BM;
        int tx = tid % (BN / TN), ty = tid / (BN / TN);
        int mb = ty * TM, nb = tx * TN;
        unsigned long long acc[TM / 2][TN];
#pragma unroll
        for (int i = 0; i < TM / 2; i++)
#pragma unroll
            for (int j = 0; j < TN; j++) acc[i][j] = 0ull;
        for (int kk = 0; kk < DD; kk += BK) {
#pragma unroll
            for (int it = 0; it < BM * BK / 4; it += 256) {
                int i = it + tid;
                int m = i / (BK / 4), k4 = (i % (BK / 4)) * 4;
                float4 v = *(const float4*)(x + (size_t)(m0 + m) * DD + kk + k4);
                As[k4 + 0][m] = v.x; As[k4 + 1][m] = v.y;
                As[k4 + 2][m] = v.z; As[k4 + 3][m] = v.w;
            }
#pragma unroll
            for (int it = 0; it < BN * BK / 4; it += 256) {
                int i = it + tid;
                int n = i / (BK / 4), k4 = (i % (BK / 4)) * 4;
                float4 v = *(const float4*)(gate_w + (size_t)n * DD + kk + k4);
                Bs[k4 + 0][n] = v.x; Bs[k4 + 1][n] = v.y;
                Bs[k4 + 2][n] = v.z; Bs[k4 + 3][n] = v.w;
            }
            __syncthreads();
#pragma unroll
            for (int k = 0; k < BK; k++) {
                unsigned long long a2[TM / 2];
                ulonglong2 av = *(const ulonglong2*)&As[k][mb];
                a2[0] = av.x; a2[1] = av.y;
                float4 b4 = *(const float4*)&Bs[k][nb];
                float bv[4] = {b4.x, b4.y, b4.z, b4.w};
#pragma unroll
                for (int j = 0; j < TN; j++) {
                    unsigned long long b2 = pack2f(bv[j]);
#pragma unroll
                    for (int i = 0; i < TM / 2; i++) acc[i][j] = ffma2(a2[i], b2, acc[i][j]);
                }
            }
            __syncthreads();
        }
#pragma unroll
        for (int i = 0; i < TM / 2; i++)
#pragma unroll
            for (int j = 0; j < TN; j++) {
                float2 u = unpack2f(acc[i][j]);
                g_logits[(size_t)(m0 + mb + 2 * i) * EE + nb + j] = u.x;
                g_logits[(size_t)(m0 + mb + 2 * i + 1) * EE + nb + j] = u.y;
            }
        return;
    }
    bx -= GATE_BLKS;
    if (bx < XS_B) { split_four(x, g_x_hi, g_x_lo, bx * 1024 + tid); return; }
    bx -= XS_B;
    if (bx < E1_B) { split_four(e1_w, g_e1w_hi, g_e1w_lo, bx * 1024 + tid); return; }
    bx -= E1_B;
    if (bx < S1_B) { split_four(sh1_w, g_s1w_hi, g_s1w_lo, bx * 1024 + tid); return; }
    bx -= S1_B;
    if (bx < E2_B) { split_four(e2_w, g_e2w_hi, g_e2w_lo, bx * 1024 + tid); return; }
    bx -= E2_B;
    if (bx < S2_B) { split_four(sh2_w, g_s2w_hi, g_s2w_lo, bx * 1024 + tid); return; }
    bx -= S2_B;
    if (bx < ZO_B) {
        int base = bx * 1024 + tid;
        float4 z = make_float4(0.f, 0.f, 0.f, 0.f);
#pragma unroll
        for (int j = 0; j < 4; j++) ((float4*)out)[base + j * 256] = z;
        return;
    }
    bx -= ZO_B;
    int i = bx * 256 + tid;
    g_ident[i] = i;
    g_ones[i] = 1.0f;
    if (i < EE) { g_counts[i] = 0; g_prob_sum[i] = 0.0f; }
}

// ---------------- unified mma.sync split-bf16 GEMM (R7/R11 proven mainloop) ----------------
// BM=128, BN=256, BK=64; 8 warps (2x4), warp tile 64x64; 2-stage 96KB cp.async stages.
static constexpr int TG_BM = 128, TG_BN = 256, TG_BK = 64;
static constexpr int STG_A_LO = 16384;
static constexpr int STG_B_HI = 32768;
static constexpr int STG_B_LO = 65536;
static constexpr int STG_SZ   = 98304;
static constexpr int TG_SMEM  = 1024 + 2 * STG_SZ;

template <int ACT, int SCALE, int CBF, int ATOMIC>
__global__ __launch_bounds__(256) void mgemm(
    // expert side
    const __nv_bfloat16* __restrict__ Ah_e, const __nv_bfloat16* __restrict__ Al_e,
    const __nv_bfloat16* __restrict__ We_h, const __nv_bfloat16* __restrict__ We_l,
    const float* __restrict__ bias_e,
    const int* __restrict__ aidx_e,
    float* __restrict__ Cf_e, __nv_bfloat16* __restrict__ Ch_e, __nv_bfloat16* __restrict__ Cl_e,
    // shared side
    const __nv_bfloat16* __restrict__ Ah_s, const __nv_bfloat16* __restrict__ Al_s,
    const __nv_bfloat16* __restrict__ Ws_h, const __nv_bfloat16* __restrict__ Ws_l,
    const float* __restrict__ bias_s,
    float* __restrict__ Cf_s, __nv_bfloat16* __restrict__ Ch_s, __nv_bfloat16* __restrict__ Cl_s,
    int lda, int ldc, int N, int K) {
    const int z = blockIdx.z;
    const bool isSh = (z == EE);
    int M;
    const __nv_bfloat16 *Ah, *Al, *Wh, *Wl;
    const float *biasp, *rsp;
    const int *aidxp, *cidxp;
    float* Cf;
    __nv_bfloat16 *Ch, *Cl;
    if (isSh) {
        M = TOK;
        Ah = Ah_s; Al = Al_s; Wh = Ws_h; Wl = Ws_l; biasp = bias_s;
        aidxp = g_ident; cidxp = g_ident; rsp = g_ones;
        Cf = Cf_s; Ch = Ch_s; Cl = Cl_s;
    } else {
        int c = g_counts[z];
        M = c < CAP ? c : CAP;
        Ah = Ah_e; Al = Al_e;
        Wh = We_h + (size_t)z * N * K; Wl = We_l + (size_t)z * N * K;
        biasp = bias_e + (size_t)z * N;
        aidxp = aidx_e + z * CAP; cidxp = g_pairidx + z * CAP; rsp = g_score + z * CAP;
        Cf = Cf_e; Ch = Ch_e; Cl = Cl_e;
    }
    int m0 = blockIdx.x * TG_BM;
    if (m0 >= M) return;
    int n0 = blockIdx.y * TG_BN;

    extern __shared__ char smem_raw[];
    uint32_t sb = smem_u32(smem_raw);
    uint32_t tiles = (sb + 1023u) & ~1023u;

    const int tid = threadIdx.x;
    const int lane = tid & 31;
    const int w = tid >> 5;
    const int wm = w & 1, wn = w >> 1;

    // ---- cp.async fill geometry ----
    const int c8 = tid & 7;
    const int r0 = tid >> 3;
    const uint32_t offBase = (uint32_t)(r0 * 128 + ((c8 ^ (r0 & 7)) << 4));
    const char* aSrc[4];
    uint32_t aSz[4];
#pragma unroll
    for (int i = 0; i < 4; i++) {
        int gm = m0 + r0 + 32 * i;
        bool v = gm < M;
        int ar = v ? aidxp[gm] : 0;
        aSrc[i] = (const char*)(Ah + (size_t)ar * lda + c8 * 8);
        aSz[i] = v ? 16u : 0u;
    }
    const ptrdiff_t dAlo = (const char*)Al - (const char*)Ah;
    const char* bSrc = (const char*)(Wh + (size_t)(n0 + r0) * K + c8 * 8);
    const ptrdiff_t dBlo = (const char*)Wl - (const char*)Wh;

#define FILL(kk, buf)                                                           \
    {                                                                           \
        uint32_t sg = tiles + (uint32_t)(buf) * STG_SZ;                         \
        _Pragma("unroll")                                                       \
        for (int i = 0; i < 4; i++) {                                           \
            const char* s = aSrc[i] + (size_t)(kk) * 2;                         \
            uint32_t d = sg + offBase + i * 4096;                               \
            cpa16(d, s, aSz[i]);                                                \
            cpa16(d + STG_A_LO, s + dAlo, aSz[i]);                              \
        }                                                                       \
        _Pragma("unroll")                                                       \
        for (int i = 0; i < 8; i++) {                                           \
            const char* s = bSrc + (size_t)(kk) * 2 + (size_t)i * 32 * K * 2;   \
            uint32_t d = sg + STG_B_HI + offBase + i * 4096;                    \
            cpa16(d, s, 16);                                                    \
            cpa16(d + 32768, s + dBlo, 16);                                     \
        }                                                                       \
    }

    // ---- ldmatrix per-lane geometry ----
    const int arow16 = (lane & 7) | (lane & 8);
    const uint32_t ak16 = (lane & 16) ? 16u : 0u;
    const int brow16 = (lane & 7) | ((lane & 16) >> 1);
    const uint32_t bk16 = (lane & 8) ? 16u : 0u;
    uint32_t artA[4], artB[4];
#pragma unroll
    for (int mi = 0; mi < 4; mi++) {
        int row = wm * 64 + mi * 16 + arow16;
        artA[mi] = (uint32_t)(row * 128) | ((uint32_t)(row & 7) << 4);
    }
#pragma unroll
    for (int nj = 0; nj < 4; nj++) {
        int row = wn * 64 + nj * 16 + brow16;
        artB[nj] = (uint32_t)(row * 128) | ((uint32_t)(row & 7) << 4);
    }

    float acc[4][8][4];
#pragma unroll
    for (int i = 0; i < 4; i++)
#pragma unroll
        for (int j = 0; j < 8; j++)
#pragma unroll
            for (int q = 0; q < 4; q++) acc[i][j][q] = 0.0f;

    const int KT = K / TG_BK;

    FILL(0, 0);
    CP_COMMIT();
    FILL(TG_BK, 1);
    CP_COMMIT();

    for (int t = 0; t < KT; t++) {
        CP_WAIT1();
        __syncthreads();
        const uint32_t sgA  = tiles + (uint32_t)(t & 1) * STG_SZ;
        const uint32_t sgAl = sgA + STG_A_LO;
        const uint32_t sgB  = sgA + STG_B_HI;
        const uint32_t sgBl = sgA + STG_B_LO;
#pragma unroll
        for (int ks = 0; ks < 4; ks++) {
            const uint32_t xA = (uint32_t)(ks * 32) + ak16;
            uint32_t ahf[4][4], alf[4][4];
#pragma unroll
            for (int mi = 0; mi < 4; mi++) {
                uint32_t off = artA[mi] ^ xA;
                LDSM4(ahf[mi], sgA + off);
                LDSM4(alf[mi], sgAl + off);
            }
            const uint32_t xB = (uint32_t)(ks * 32) + bk16;
#pragma unroll
            for (int nj = 0; nj < 4; nj++) {
                uint32_t bh[4], bl[4];
                uint32_t off = artB[nj] ^ xB;
                LDSM4(bh, sgB + off);
                LDSM4(bl, sgBl + off);
#pragma unroll
                for (int mi = 0; mi < 4; mi++) {
                    hmma(acc[mi][2 * nj],     ahf[mi], bh[0], bh[1]);
                    hmma(acc[mi][2 * nj + 1], ahf[mi], bh[2], bh[3]);
                }
#pragma unroll
                for (int mi = 0; mi < 4; mi++) {
                    hmma(acc[mi][2 * nj],     ahf[mi], bl[0], bl[1]);
                    hmma(acc[mi][2 * nj + 1], ahf[mi], bl[2], bl[3]);
                }
#pragma unroll
                for (int mi = 0; mi < 4; mi++) {
                    hmma(acc[mi][2 * nj],     alf[mi], bh[0], bh[1]);
                    hmma(acc[mi][2 * nj + 1], alf[mi], bh[2], bh[3]);
                }
            }
        }
        __syncthreads();
        if (t + 2 < KT) FILL((t + 2) * TG_BK, t & 1);
        CP_COMMIT();
    }
#undef FILL

    // ---- epilogue ----
    const int g = lane >> 2, q2 = (lane & 3) * 2;
#pragma unroll
    for (int mi = 0; mi < 4; mi++) {
        int ml = m0 + wm * 64 + mi * 16 + g;
        int mh = ml + 8;
        bool vlo = ml < M, vhi = mh < M;
        int cr0 = 0, cr1 = 0;
        float s0 = 1.0f, s1 = 1.0f;
        if (vlo) { cr0 = cidxp[ml]; if (SCALE) s0 = rsp[ml]; }
        if (vhi) { cr1 = cidxp[mh]; if (SCALE) s1 = rsp[mh]; }
        if (ATOMIC) {
            if (vlo && !isSh) cr0 = cr0 / TOPK;
            if (vhi && !isSh) cr1 = cr1 / TOPK;
        }
#pragma unroll
        for (int nf = 0; nf < 8; nf++) {
            int gn = n0 + wn * 64 + nf * 8 + q2;
            float b0 = biasp[gn], b1 = biasp[gn + 1];
            float v0 = acc[mi][nf][0] + b0, v1 = acc[mi][nf][1] + b1;
            float v2 = acc[mi][nf][2] + b0, v3 = acc[mi][nf][3] + b1;
            if (ACT) { v0 = gelu_ex(v0); v1 = gelu_ex(v1); v2 = gelu_ex(v2); v3 = gelu_ex(v3); }
            if (SCALE) { v0 *= s0; v1 *= s0; v2 *= s1; v3 *= s1; }
            if (!CBF) {
                if (ATOMIC) {
                    if (vlo) {
                        float* p = Cf + (size_t)cr0 * ldc + gn;
                        atomicAdd(p, v0); atomicAdd(p + 1, v1);
                    }
                    if (vhi) {
                        float* p = Cf + (size_t)cr1 * ldc + gn;
                        atomicAdd(p, v2); atomicAdd(p + 1, v3);
                    }
                } else {
                    if (vlo) *(float2*)(Cf + (size_t)cr0 * ldc + gn) = make_float2(v0, v1);
                    if (vhi) *(float2*)(Cf + (size_t)cr1 * ldc + gn) = make_float2(v2, v3);
                }
            } else {
                if (vlo) {
                    uint32_t h, l;
                    split2(v0, v1, h, l);
                    *(uint32_t*)(Ch + (size_t)cr0 * ldc + gn) = h;
                    *(uint32_t*)(Cl + (size_t)cr0 * ldc + gn) = l;
                }
                if (vhi) {
                    uint32_t h, l;
                    split2(v2, v3, h, l);
                    *(uint32_t*)(Ch + (size_t)cr1 * ldc + gn) = h;
                    *(uint32_t*)(Cl + (size_t)cr1 * ldc + gn) = l;
                }
            }
        }
    }
}

// ---------------- softmax + top-k + routing + prob accumulation ----------------
__global__ void topk_route_kernel() {
    int gw = (blockIdx.x * blockDim.x + threadIdx.x) >> 5;
    int lane = threadIdx.x & 31;
    if (gw >= TOK) return;
    float2 v = ((const float2*)(g_logits + (size_t)gw * EE))[lane];
    float m = fmaxf(v.x, v.y);
#pragma unroll
    for (int o = 16; o > 0; o >>= 1) m = fmaxf(m, __shfl_xor_sync(FULLMASK, m, o));
    float e0 = __expf(v.x - m), e1 = __expf(v.y - m);
    float s = e0 + e1;
#pragma unroll
    for (int o = 16; o > 0; o >>= 1) s += __shfl_xor_sync(FULLMASK, s, o);
    float inv = 1.0f / s;
    float p0 = e0 * inv, p1 = e1 * inv;
    atomicAdd(&g_prob_sum[2 * lane], p0);
    atomicAdd(&g_prob_sum[2 * lane + 1], p1);

    float a0 = p0, a1 = p1;
    for (int k = 0; k < TOPK; k++) {
        float bvv; int bi;
        if (a0 >= a1) { bvv = a0; bi = 2 * lane; }
        else          { bvv = a1; bi = 2 * lane + 1; }
#pragma unroll
        for (int o = 16; o > 0; o >>= 1) {
            float ov = __shfl_xor_sync(FULLMASK, bvv, o);
            int oi = __shfl_xor_sync(FULLMASK, bi, o);
            if (ov > bvv || (ov == bvv && oi < bi)) { bvv = ov; bi = oi; }
        }
        if ((bi >> 1) == lane) {
            if (bi & 1) a1 = -1.0f; else a0 = -1.0f;
            int slot = atomicAdd(&g_counts[bi], 1);
            if (slot < CAP) {
                int base = bi * CAP + slot;
                g_tok[base] = gw;
                g_pairidx[base] = gw * TOPK + k;
                g_score[base] = bvv;
            }
        }
    }
}

// ---------------- scalar outputs ----------------
__global__ void finalize_kernel(float* __restrict__ out) {
    __shared__ float sh[EE];
    int e = threadIdx.x;
    float freq = (float)g_counts[e] / (float)(TOK * TOPK);
    float prob = g_prob_sum[e] * (1.0f / (float)TOK);
    out[OUT_MAIN + 1 + e] = freq;
    out[OUT_MAIN + 1 + EE + e] = prob;
    sh[e] = freq * prob;
    __syncthreads();
    if (e == 0) {
        float s = 0.0f;
        for (int i = 0; i < EE; i++) s += sh[i];
        out[OUT_MAIN] = 0.01f * s;
    }
}

// ---------------- launch ----------------
extern "C" void kernel_launch(void* const* d_in, const int* in_sizes, int n_in,
                              void* d_out, int out_size) {
    const float* x      = (const float*)d_in[0];
    const float* gate_w = (const float*)d_in[1];
    const float* sh1_w  = (const float*)d_in[2];
    const float* sh1_b  = (const float*)d_in[3];
    const float* sh2_w  = (const float*)d_in[4];
    const float* sh2_b  = (const float*)d_in[5];
    const float* e1_w   = (const float*)d_in[6];
    const float* e1_b   = (const float*)d_in[7];
    const float* e2_w   = (const float*)d_in[8];
    const float* e2_b   = (const float*)d_in[9];
    float* out = (float*)d_out;

    int *p_tok, *p_pair;
    __nv_bfloat16 *p_x_hi, *p_x_lo, *p_s1h, *p_s1l, *p_s2h, *p_s2l;
    __nv_bfloat16 *p_e1h, *p_e1l, *p_e2h, *p_e2l;
    __nv_bfloat16 *p_shh_hi, *p_shh_lo, *p_h_hi, *p_h_lo;
    cudaGetSymbolAddress((void**)&p_tok, g_tok);
    cudaGetSymbolAddress((void**)&p_pair, g_pairidx);
    cudaGetSymbolAddress((void**)&p_x_hi, g_x_hi);
    cudaGetSymbolAddress((void**)&p_x_lo, g_x_lo);
    cudaGetSymbolAddress((void**)&p_s1h, g_s1w_hi);
    cudaGetSymbolAddress((void**)&p_s1l, g_s1w_lo);
    cudaGetSymbolAddress((void**)&p_s2h, g_s2w_hi);
    cudaGetSymbolAddress((void**)&p_s2l, g_s2w_lo);
    cudaGetSymbolAddress((void**)&p_e1h, g_e1w_hi);
    cudaGetSymbolAddress((void**)&p_e1l, g_e1w_lo);
    cudaGetSymbolAddress((void**)&p_e2h, g_e2w_hi);
    cudaGetSymbolAddress((void**)&p_e2l, g_e2w_lo);
    cudaGetSymbolAddress((void**)&p_shh_hi, g_shh_hi);
    cudaGetSymbolAddress((void**)&p_shh_lo, g_shh_lo);
    cudaGetSymbolAddress((void**)&p_h_hi, g_h_hi);
    cudaGetSymbolAddress((void**)&p_h_lo, g_h_lo);

    cudaFuncSetAttribute(mgemm<1, 0, 1, 0>,
                         cudaFuncAttributeMaxDynamicSharedMemorySize, TG_SMEM);
    cudaFuncSetAttribute(mgemm<0, 1, 0, 1>,
                         cudaFuncAttributeMaxDynamicSharedMemorySize, TG_SMEM);

    // fused prep: gate GEMM + all hi/lo splits (4x ILP) + zero(out) + reset
    prep_kernel<<<PREP_BLKS, 256>>>(x, gate_w, e1_w, sh1_w, e2_w, sh2_w, out);

    topk_route_kernel<<<TOK / 8, 256>>>();
    finalize_kernel<<<1, 64>>>(out);

    // GEMM1: experts (gather tok -> h) + shared (x -> shh)
    mgemm<1, 0, 1, 0><<<dim3(TOK / 128, HH / 256, EE + 1), 256, TG_SMEM>>>(
        p_x_hi, p_x_lo, p_e1h, p_e1l, e1_b, p_tok,
        nullptr, p_h_hi, p_h_lo,
        p_x_hi, p_x_lo, p_s1h, p_s1l, sh1_b,
        nullptr, p_shh_hi, p_shh_lo,
        DD, HH, HH, DD);

    // GEMM2: experts + shared; fused combine via atomicAdd into out
    mgemm<0, 1, 0, 1><<<dim3(TOK / 128, DD / 256, EE + 1), 256, TG_SMEM>>>(
        p_h_hi, p_h_lo, p_e2h, p_e2l, e2_b, p_pair,
        out, nullptr, nullptr,
        p_shh_hi, p_shh_lo, p_s2h, p_s2l, sh2_b,
        out, nullptr, nullptr,
        HH, DD, DD, HH);
}

// round 14
// speedup vs baseline: 1.0215x; 1.0215x over previous
#include <cuda_runtime.h>
#include <cuda_bf16.h>
#include <math.h>
#include <stdint.h>

// ---------------- problem constants ----------------
static constexpr int TOK   = 4096;
static constexpr int DD    = 768;
static constexpr int HH    = 1536;
static constexpr int EE    = 64;
static constexpr int TOPK  = 6;
static constexpr int CAP   = 1536;
static constexpr int NPAIR = TOK * TOPK;
static constexpr int OUT_MAIN = TOK * DD;

#define FULLMASK 0xFFFFFFFFu

// ---------------- scratch ----------------
__device__ float g_logits[TOK * EE];
__device__ float g_prob_sum[EE];
__device__ int   g_counts[EE];
__device__ int   g_tok[EE * CAP];
__device__ int   g_pairidx[EE * CAP];
__device__ float g_score[EE * CAP];
__device__ int   g_ident[TOK];
__device__ float g_ones[TOK];
__device__ __nv_bfloat16 g_x_hi[(size_t)TOK * DD];
__device__ __nv_bfloat16 g_x_lo[(size_t)TOK * DD];
__device__ __nv_bfloat16 g_s1w_hi[(size_t)HH * DD];
__device__ __nv_bfloat16 g_s1w_lo[(size_t)HH * DD];
__device__ __nv_bfloat16 g_s2w_hi[(size_t)DD * HH];
__device__ __nv_bfloat16 g_s2w_lo[(size_t)DD * HH];
__device__ __nv_bfloat16 g_e1w_hi[(size_t)EE * HH * DD];
__device__ __nv_bfloat16 g_e1w_lo[(size_t)EE * HH * DD];
__device__ __nv_bfloat16 g_e2w_hi[(size_t)EE * DD * HH];
__device__ __nv_bfloat16 g_e2w_lo[(size_t)EE * DD * HH];
__device__ __nv_bfloat16 g_shh_hi[(size_t)TOK * HH];
__device__ __nv_bfloat16 g_shh_lo[(size_t)TOK * HH];
__device__ __nv_bfloat16 g_h_hi[(size_t)NPAIR * HH];
__device__ __nv_bfloat16 g_h_lo[(size_t)NPAIR * HH];

static constexpr int XS_N8 = TOK * DD / 8;
static constexpr int S1_N8 = HH * DD / 8;
static constexpr int S2_N8 = DD * HH / 8;
static constexpr int E1_N8 = EE * HH * DD / 8;
static constexpr int E2_N8 = EE * DD * HH / 8;

// ---------------- helpers ----------------
__device__ __forceinline__ uint32_t smem_u32(const void* p) {
    uint32_t a;
    asm("{ .reg .u64 t; cvta.to.shared.u64 t, %1; cvt.u32.u64 %0, t; }" : "=r"(a) : "l"(p));
    return a;
}
__device__ __forceinline__ uint32_t cvt_bf2(float hi_upper, float lo_lower) {
    uint32_t r;
    asm("cvt.rn.bf16x2.f32 %0, %1, %2;" : "=r"(r) : "f"(hi_upper), "f"(lo_lower));
    return r;
}
__device__ __forceinline__ void split2(float v0, float v1, uint32_t& h, uint32_t& l) {
    h = cvt_bf2(v1, v0);
    float f0 = __uint_as_float(h << 16);
    float f1 = __uint_as_float(h & 0xffff0000u);
    l = cvt_bf2(v1 - f1, v0 - f0);
}
__device__ __forceinline__ void split_one(const float* __restrict__ src,
                                          __nv_bfloat16* __restrict__ hi,
                                          __nv_bfloat16* __restrict__ lo, int i) {
    const float4* s = (const float4*)src + (size_t)i * 2;
    float4 v0 = s[0], v1 = s[1];
    uint32_t h0, l0, h1, l1, h2, l2, h3, l3;
    split2(v0.x, v0.y, h0, l0);
    split2(v0.z, v0.w, h1, l1);
    split2(v1.x, v1.y, h2, l2);
    split2(v1.z, v1.w, h3, l3);
    ((uint4*)hi)[i] = make_uint4(h0, h1, h2, h3);
    ((uint4*)lo)[i] = make_uint4(l0, l1, l2, l3);
}
__device__ __forceinline__ float gelu_ex(float x) {
    return 0.5f * x * (1.0f + erff(x * 0.70710678118654752f));
}
__device__ __forceinline__ void hmma(float* c, const uint32_t* a, uint32_t b0, uint32_t b1) {
    asm volatile(
        "mma.sync.aligned.m16n8k16.row.col.f32.bf16.bf16.f32 "
        "{%0,%1,%2,%3}, {%4,%5,%6,%7}, {%8,%9}, {%0,%1,%2,%3};"
        : "+f"(c[0]), "+f"(c[1]), "+f"(c[2]), "+f"(c[3])
        : "r"(a[0]), "r"(a[1]), "r"(a[2]), "r"(a[3]), "r"(b0), "r"(b1));
}
#define LDSM4(r, a) \
    asm volatile("ldmatrix.sync.aligned.m8n8.x4.shared.b16 {%0,%1,%2,%3}, [%4];" \
                 : "=r"((r)[0]), "=r"((r)[1]), "=r"((r)[2]), "=r"((r)[3]) : "r"(a))
__device__ __forceinline__ void cpa16(uint32_t dst, const void* src, uint32_t srcsz) {
    asm volatile("cp.async.cg.shared.global [%0], [%1], 16, %2;"
                 :: "r"(dst), "l"(src), "r"(srcsz));
}
#define CP_COMMIT() asm volatile("cp.async.commit_group;" ::: "memory")
#define CP_WAIT1()  asm volatile("cp.async.wait_group 1;" ::: "memory")

__device__ __forceinline__ unsigned long long ffma2(unsigned long long a,
                                                    unsigned long long b,
                                                    unsigned long long c) {
    unsigned long long d;
    asm("fma.rn.f32x2 %0, %1, %2, %3;" : "=l"(d) : "l"(a), "l"(b), "l"(c));
    return d;
}
__device__ __forceinline__ unsigned long long pack2f(float x) {
    unsigned long long d;
    asm("mov.b64 %0, {%1, %1};" : "=l"(d) : "f"(x));
    return d;
}
__device__ __forceinline__ float2 unpack2f(unsigned long long v) {
    float2 r;
    asm("mov.b64 {%0, %1}, %2;" : "=f"(r.x), "=f"(r.y) : "l"(v));
    return r;
}

// ---------------- fused prep (R11-exact): gate GEMM + splits + zero-out + reset ----------------
static constexpr int GATE_BLKS = 64;
static constexpr int XS_B = XS_N8 / 256;
static constexpr int E1_B = E1_N8 / 256;
static constexpr int S1_B = S1_N8 / 256;
static constexpr int E2_B = E2_N8 / 256;
static constexpr int S2_B = S2_N8 / 256;
static constexpr int ZO_B = TOK * DD / 4 / 256;
static constexpr int RS_B = TOK / 256;
static constexpr int PREP_BLKS =
    GATE_BLKS + XS_B + E1_B + S1_B + E2_B + S2_B + ZO_B + RS_B;

__global__ __launch_bounds__(256) void prep_kernel(
    const float* __restrict__ x, const float* __restrict__ gate_w,
    const float* __restrict__ e1_w, const float* __restrict__ sh1_w,
    const float* __restrict__ e2_w, const float* __restrict__ sh2_w,
    float* __restrict__ out) {
    int bx = blockIdx.x;
    int tid = threadIdx.x;
    if (bx < GATE_BLKS) {
        constexpr int BM = 64, BN = 64, BK = 16, TM = 4, TN = 4;
        __shared__ __align__(16) float As[BK][BM + 4];
        __shared__ __align__(16) float Bs[BK][BN + 4];
        int m0 = bx * BM;
        int tx = tid % (BN / TN), ty = tid / (BN / TN);
        int mb = ty * TM, nb = tx * TN;
        unsigned long long acc[TM / 2][TN];
#pragma unroll
        for (int i = 0; i < TM / 2; i++)
#pragma unroll
            for (int j = 0; j < TN; j++) acc[i][j] = 0ull;
        for (int kk = 0; kk < DD; kk += BK) {
#pragma unroll
            for (int it = 0; it < BM * BK / 4; it += 256) {
                int i = it + tid;
                int m = i / (BK / 4), k4 = (i % (BK / 4)) * 4;
                float4 v = *(const float4*)(x + (size_t)(m0 + m) * DD + kk + k4);
                As[k4 + 0][m] = v.x; As[k4 + 1][m] = v.y;
                As[k4 + 2][m] = v.z; As[k4 + 3][m] = v.w;
            }
#pragma unroll
            for (int it = 0; it < BN * BK / 4; it += 256) {
                int i = it + tid;
                int n = i / (BK / 4), k4 = (i % (BK / 4)) * 4;
                float4 v = *(const float4*)(gate_w + (size_t)n * DD + kk + k4);
                Bs[k4 + 0][n] = v.x; Bs[k4 + 1][n] = v.y;
                Bs[k4 + 2][n] = v.z; Bs[k4 + 3][n] = v.w;
            }
            __syncthreads();
#pragma unroll
            for (int k = 0; k < BK; k++) {
                unsigned long long a2[TM / 2];
                ulonglong2 av = *(const ulonglong2*)&As[k][mb];
                a2[0] = av.x; a2[1] = av.y;
                float4 b4 = *(const float4*)&Bs[k][nb];
                float bv[4] = {b4.x, b4.y, b4.z, b4.w};
#pragma unroll
                for (int j = 0; j < TN; j++) {
                    unsigned long long b2 = pack2f(bv[j]);
#pragma unroll
                    for (int i = 0; i < TM / 2; i++) acc[i][j] = ffma2(a2[i], b2, acc[i][j]);
                }
            }
            __syncthreads();
        }
#pragma unroll
        for (int i = 0; i < TM / 2; i++)
#pragma unroll
            for (int j = 0; j < TN; j++) {
                float2 u = unpack2f(acc[i][j]);
                g_logits[(size_t)(m0 + mb + 2 * i) * EE + nb + j] = u.x;
                g_logits[(size_t)(m0 + mb + 2 * i + 1) * EE + nb + j] = u.y;
            }
        return;
    }
    bx -= GATE_BLKS;
    if (bx < XS_B) { split_one(x, g_x_hi, g_x_lo, bx * 256 + tid); return; }
    bx -= XS_B;
    if (bx < E1_B) { split_one(e1_w, g_e1w_hi, g_e1w_lo, bx * 256 + tid); return; }
    bx -= E1_B;
    if (bx < S1_B) { split_one(sh1_w, g_s1w_hi, g_s1w_lo, bx * 256 + tid); return; }
    bx -= S1_B;
    if (bx < E2_B) { split_one(e2_w, g_e2w_hi, g_e2w_lo, bx * 256 + tid); return; }
    bx -= E2_B;
    if (bx < S2_B) { split_one(sh2_w, g_s2w_hi, g_s2w_lo, bx * 256 + tid); return; }
    bx -= S2_B;
    if (bx < ZO_B) {
        ((float4*)out)[bx * 256 + tid] = make_float4(0.f, 0.f, 0.f, 0.f);
        return;
    }
    bx -= ZO_B;
    int i = bx * 256 + tid;
    g_ident[i] = i;
    g_ones[i] = 1.0f;
    if (i < EE) { g_counts[i] = 0; g_prob_sum[i] = 0.0f; }
}

// ---------------- 2-CTA/SM mma.sync split-bf16 GEMM ----------------
// BM=128, BN=128, BK=32; 8 warps (2x4), warp tile 64x32; hi/lo packed per 128B row.
// Stage = 32KB (A 16KB + B 16KB); 2 stages; 2 CTAs/SM hide sync bubbles.
static constexpr int TG_BM = 128, TG_BN = 128, TG_BK = 32;
static constexpr int STG_B  = 16384;
static constexpr int STG_SZ = 32768;
static constexpr int TG_SMEM = 1024 + 2 * STG_SZ;   // 66560

template <int ACT, int SCALE, int CBF, int ATOMIC>
__global__ __launch_bounds__(256, 2) void mgemm(
    // expert side
    const __nv_bfloat16* __restrict__ Ah_e, const __nv_bfloat16* __restrict__ Al_e,
    const __nv_bfloat16* __restrict__ We_h, const __nv_bfloat16* __restrict__ We_l,
    const float* __restrict__ bias_e,
    const int* __restrict__ aidx_e,
    float* __restrict__ Cf_e, __nv_bfloat16* __restrict__ Ch_e, __nv_bfloat16* __restrict__ Cl_e,
    // shared side
    const __nv_bfloat16* __restrict__ Ah_s, const __nv_bfloat16* __restrict__ Al_s,
    const __nv_bfloat16* __restrict__ Ws_h, const __nv_bfloat16* __restrict__ Ws_l,
    const float* __restrict__ bias_s,
    float* __restrict__ Cf_s, __nv_bfloat16* __restrict__ Ch_s, __nv_bfloat16* __restrict__ Cl_s,
    int lda, int ldc, int N, int K) {
    const int z = blockIdx.z;
    const bool isSh = (z == EE);
    int M;
    const __nv_bfloat16 *Ah, *Al, *Wh, *Wl;
    const float *biasp, *rsp;
    const int *aidxp, *cidxp;
    float* Cf;
    __nv_bfloat16 *Ch, *Cl;
    if (isSh) {
        M = TOK;
        Ah = Ah_s; Al = Al_s; Wh = Ws_h; Wl = Ws_l; biasp = bias_s;
        aidxp = g_ident; cidxp = g_ident; rsp = g_ones;
        Cf = Cf_s; Ch = Ch_s; Cl = Cl_s;
    } else {
        int c = g_counts[z];
        M = c < CAP ? c : CAP;
        Ah = Ah_e; Al = Al_e;
        Wh = We_h + (size_t)z * N * K; Wl = We_l + (size_t)z * N * K;
        biasp = bias_e + (size_t)z * N;
        aidxp = aidx_e + z * CAP; cidxp = g_pairidx + z * CAP; rsp = g_score + z * CAP;
        Cf = Cf_e; Ch = Ch_e; Cl = Cl_e;
    }
    int m0 = blockIdx.x * TG_BM;
    if (m0 >= M) return;
    int n0 = blockIdx.y * TG_BN;

    extern __shared__ char smem_raw[];
    uint32_t sb = smem_u32(smem_raw);
    uint32_t tiles = (sb + 1023u) & ~1023u;

    const int tid = threadIdx.x;
    const int lane = tid & 31;
    const int w = tid >> 5;
    const int wm = w & 1, wn = w >> 1;          // 2x4 warp grid, 64x32 tiles

    // ---- cp.async fill geometry (hi/lo packed rows, R5-verified) ----
    const int c8 = tid & 7;                     // 16B chunk in 128B row
    const int r0 = tid >> 3;                    // 0..31
    const bool isHi = c8 < 4;
    const int kcol = (c8 & 3) * 8;              // k element offset
    const uint32_t offBase = (uint32_t)(r0 * 128 + ((c8 ^ (r0 & 7)) << 4));
    const char* aSrc[4];
    uint32_t aSz[4];
#pragma unroll
    for (int i = 0; i < 4; i++) {
        int gm = m0 + r0 + 32 * i;
        bool v = gm < M;
        int ar = v ? aidxp[gm] : 0;
        const __nv_bfloat16* base = isHi ? Ah : Al;
        aSrc[i] = (const char*)(base + (size_t)ar * lda + kcol);
        aSz[i] = v ? 16u : 0u;
    }
    const char* bSrc = (const char*)((isHi ? Wh : Wl) + (size_t)(n0 + r0) * K + kcol);

#define FILL(kk, buf)                                                             \
    {                                                                             \
        uint32_t sg = tiles + (uint32_t)(buf) * STG_SZ;                           \
        _Pragma("unroll")                                                         \
        for (int i = 0; i < 4; i++)                                               \
            cpa16(sg + offBase + i * 4096, aSrc[i] + (size_t)(kk) * 2, aSz[i]);   \
        _Pragma("unroll")                                                         \
        for (int i = 0; i < 4; i++)                                               \
            cpa16(sg + STG_B + offBase + i * 4096,                                \
                  bSrc + (size_t)(kk) * 2 + (size_t)i * 32 * K * 2, 16);          \
    }

    // ---- ldmatrix per-lane geometry ----
    const int arow16 = (lane & 7) | (lane & 8);
    const uint32_t ak = (lane & 16) ? 1u : 0u;
    const int brow16 = (lane & 7) | ((lane & 16) >> 1);
    const uint32_t bk = (lane & 8) ? 1u : 0u;
    uint32_t artA[4], artB[2];
#pragma unroll
    for (int mi = 0; mi < 4; mi++) {
        int row = wm * 64 + mi * 16 + arow16;
        artA[mi] = (uint32_t)(row * 128) | ((uint32_t)(row & 7) << 4);
    }
#pragma unroll
    for (int nj = 0; nj < 2; nj++) {
        int row = wn * 32 + nj * 16 + brow16;
        artB[nj] = (uint32_t)(row * 128) | ((uint32_t)(row & 7) << 4);
    }

    float acc[4][4][4];
#pragma unroll
    for (int i = 0; i < 4; i++)
#pragma unroll
        for (int j = 0; j < 4; j++)
#pragma unroll
            for (int q = 0; q < 4; q++) acc[i][j][q] = 0.0f;

    const int KT = K / TG_BK;

    FILL(0, 0);
    CP_COMMIT();
    FILL(TG_BK, 1);
    CP_COMMIT();

    for (int t = 0; t < KT; t++) {
        CP_WAIT1();
        __syncthreads();
        const uint32_t sgA = tiles + (uint32_t)(t & 1) * STG_SZ;
        const uint32_t sgB = sgA + STG_B;
#pragma unroll
        for (int ks = 0; ks < 2; ks++) {
            const uint32_t cA = (uint32_t)(ks * 2) + ak;      // hi chunk 0..3
            uint32_t ahf[4][4], alf[4][4];
#pragma unroll
            for (int mi = 0; mi < 4; mi++) {
                LDSM4(ahf[mi], sgA + (artA[mi] ^ (cA << 4)));
                LDSM4(alf[mi], sgA + (artA[mi] ^ ((cA + 4) << 4)));
            }
            const uint32_t cB = (uint32_t)(ks * 2) + bk;
#pragma unroll
            for (int nj = 0; nj < 2; nj++) {
                uint32_t bh[4], bl[4];
                LDSM4(bh, sgB + (artB[nj] ^ (cB << 4)));
                LDSM4(bl, sgB + (artB[nj] ^ ((cB + 4) << 4)));
#pragma unroll
                for (int mi = 0; mi < 4; mi++) {
                    hmma(acc[mi][2 * nj],     ahf[mi], bh[0], bh[1]);
                    hmma(acc[mi][2 * nj + 1], ahf[mi], bh[2], bh[3]);
                }
#pragma unroll
                for (int mi = 0; mi < 4; mi++) {
                    hmma(acc[mi][2 * nj],     ahf[mi], bl[0], bl[1]);
                    hmma(acc[mi][2 * nj + 1], ahf[mi], bl[2], bl[3]);
                }
#pragma unroll
                for (int mi = 0; mi < 4; mi++) {
                    hmma(acc[mi][2 * nj],     alf[mi], bh[0], bh[1]);
                    hmma(acc[mi][2 * nj + 1], alf[mi], bh[2], bh[3]);
                }
            }
        }
        __syncthreads();
        if (t + 2 < KT) FILL((t + 2) * TG_BK, t & 1);
        CP_COMMIT();
    }
#undef FILL

    // ---- epilogue ----
    const int g = lane >> 2, q2 = (lane & 3) * 2;
#pragma unroll
    for (int mi = 0; mi < 4; mi++) {
        int ml = m0 + wm * 64 + mi * 16 + g;
        int mh = ml + 8;
        bool vlo = ml < M, vhi = mh < M;
        int cr0 = 0, cr1 = 0;
        float s0 = 1.0f, s1 = 1.0f;
        if (vlo) { cr0 = cidxp[ml]; if (SCALE) s0 = rsp[ml]; }
        if (vhi) { cr1 = cidxp[mh]; if (SCALE) s1 = rsp[mh]; }
        if (ATOMIC) {
            if (vlo && !isSh) cr0 = cr0 / TOPK;
            if (vhi && !isSh) cr1 = cr1 / TOPK;
        }
#pragma unroll
        for (int nf = 0; nf < 4; nf++) {
            int gn = n0 + wn * 32 + nf * 8 + q2;
            float b0 = biasp[gn], b1 = biasp[gn + 1];
            float v0 = acc[mi][nf][0] + b0, v1 = acc[mi][nf][1] + b1;
            float v2 = acc[mi][nf][2] + b0, v3 = acc[mi][nf][3] + b1;
            if (ACT) { v0 = gelu_ex(v0); v1 = gelu_ex(v1); v2 = gelu_ex(v2); v3 = gelu_ex(v3); }
            if (SCALE) { v0 *= s0; v1 *= s0; v2 *= s1; v3 *= s1; }
            if (!CBF) {
                if (ATOMIC) {
                    if (vlo) {
                        float* p = Cf + (size_t)cr0 * ldc + gn;
                        atomicAdd(p, v0); atomicAdd(p + 1, v1);
                    }
                    if (vhi) {
                        float* p = Cf + (size_t)cr1 * ldc + gn;
                        atomicAdd(p, v2); atomicAdd(p + 1, v3);
                    }
                } else {
                    if (vlo) *(float2*)(Cf + (size_t)cr0 * ldc + gn) = make_float2(v0, v1);
                    if (vhi) *(float2*)(Cf + (size_t)cr1 * ldc + gn) = make_float2(v2, v3);
                }
            } else {
                if (vlo) {
                    uint32_t h, l;
                    split2(v0, v1, h, l);
                    *(uint32_t*)(Ch + (size_t)cr0 * ldc + gn) = h;
                    *(uint32_t*)(Cl + (size_t)cr0 * ldc + gn) = l;
                }
                if (vhi) {
                    uint32_t h, l;
                    split2(v2, v3, h, l);
                    *(uint32_t*)(Ch + (size_t)cr1 * ldc + gn) = h;
                    *(uint32_t*)(Cl + (size_t)cr1 * ldc + gn) = l;
                }
            }
        }
    }
}

// ---------------- softmax + top-k + routing + prob accumulation ----------------
__global__ void topk_route_kernel() {
    int gw = (blockIdx.x * blockDim.x + threadIdx.x) >> 5;
    int lane = threadIdx.x & 31;
    if (gw >= TOK) return;
    float2 v = ((const float2*)(g_logits + (size_t)gw * EE))[lane];
    float m = fmaxf(v.x, v.y);
#pragma unroll
    for (int o = 16; o > 0; o >>= 1) m = fmaxf(m, __shfl_xor_sync(FULLMASK, m, o));
    float e0 = __expf(v.x - m), e1 = __expf(v.y - m);
    float s = e0 + e1;
#pragma unroll
    for (int o = 16; o > 0; o >>= 1) s += __shfl_xor_sync(FULLMASK, s, o);
    float inv = 1.0f / s;
    float p0 = e0 * inv, p1 = e1 * inv;
    atomicAdd(&g_prob_sum[2 * lane], p0);
    atomicAdd(&g_prob_sum[2 * lane + 1], p1);

    float a0 = p0, a1 = p1;
    for (int k = 0; k < TOPK; k++) {
        float bvv; int bi;
        if (a0 >= a1) { bvv = a0; bi = 2 * lane; }
        else          { bvv = a1; bi = 2 * lane + 1; }
#pragma unroll
        for (int o = 16; o > 0; o >>= 1) {
            float ov = __shfl_xor_sync(FULLMASK, bvv, o);
            int oi = __shfl_xor_sync(FULLMASK, bi, o);
            if (ov > bvv || (ov == bvv && oi < bi)) { bvv = ov; bi = oi; }
        }
        if ((bi >> 1) == lane) {
            if (bi & 1) a1 = -1.0f; else a0 = -1.0f;
            int slot = atomicAdd(&g_counts[bi], 1);
            if (slot < CAP) {
                int base = bi * CAP + slot;
                g_tok[base] = gw;
                g_pairidx[base] = gw * TOPK + k;
                g_score[base] = bvv;
            }
        }
    }
}

// ---------------- scalar outputs ----------------
__global__ void finalize_kernel(float* __restrict__ out) {
    __shared__ float sh[EE];
    int e = threadIdx.x;
    float freq = (float)g_counts[e] / (float)(TOK * TOPK);
    float prob = g_prob_sum[e] * (1.0f / (float)TOK);
    out[OUT_MAIN + 1 + e] = freq;
    out[OUT_MAIN + 1 + EE + e] = prob;
    sh[e] = freq * prob;
    __syncthreads();
    if (e == 0) {
        float s = 0.0f;
        for (int i = 0; i < EE; i++) s += sh[i];
        out[OUT_MAIN] = 0.01f * s;
    }
}

// ---------------- launch ----------------
extern "C" void kernel_launch(void* const* d_in, const int* in_sizes, int n_in,
                              void* d_out, int out_size) {
    const float* x      = (const float*)d_in[0];
    const float* gate_w = (const float*)d_in[1];
    const float* sh1_w  = (const float*)d_in[2];
    const float* sh1_b  = (const float*)d_in[3];
    const float* sh2_w  = (const float*)d_in[4];
    const float* sh2_b  = (const float*)d_in[5];
    const float* e1_w   = (const float*)d_in[6];
    const float* e1_b   = (const float*)d_in[7];
    const float* e2_w   = (const float*)d_in[8];
    const float* e2_b   = (const float*)d_in[9];
    float* out = (float*)d_out;

    int *p_tok, *p_pair;
    __nv_bfloat16 *p_x_hi, *p_x_lo, *p_s1h, *p_s1l, *p_s2h, *p_s2l;
    __nv_bfloat16 *p_e1h, *p_e1l, *p_e2h, *p_e2l;
    __nv_bfloat16 *p_shh_hi, *p_shh_lo, *p_h_hi, *p_h_lo;
    cudaGetSymbolAddress((void**)&p_tok, g_tok);
    cudaGetSymbolAddress((void**)&p_pair, g_pairidx);
    cudaGetSymbolAddress((void**)&p_x_hi, g_x_hi);
    cudaGetSymbolAddress((void**)&p_x_lo, g_x_lo);
    cudaGetSymbolAddress((void**)&p_s1h, g_s1w_hi);
    cudaGetSymbolAddress((void**)&p_s1l, g_s1w_lo);
    cudaGetSymbolAddress((void**)&p_s2h, g_s2w_hi);
    cudaGetSymbolAddress((void**)&p_s2l, g_s2w_lo);
    cudaGetSymbolAddress((void**)&p_e1h, g_e1w_hi);
    cudaGetSymbolAddress((void**)&p_e1l, g_e1w_lo);
    cudaGetSymbolAddress((void**)&p_e2h, g_e2w_hi);
    cudaGetSymbolAddress((void**)&p_e2l, g_e2w_lo);
    cudaGetSymbolAddress((void**)&p_shh_hi, g_shh_hi);
    cudaGetSymbolAddress((void**)&p_shh_lo, g_shh_lo);
    cudaGetSymbolAddress((void**)&p_h_hi, g_h_hi);
    cudaGetSymbolAddress((void**)&p_h_lo, g_h_lo);

    cudaFuncSetAttribute(mgemm<1, 0, 1, 0>,
                         cudaFuncAttributeMaxDynamicSharedMemorySize, TG_SMEM);
    cudaFuncSetAttribute(mgemm<0, 1, 0, 1>,
                         cudaFuncAttributeMaxDynamicSharedMemorySize, TG_SMEM);

    // fused prep (R11-exact)
    prep_kernel<<<PREP_BLKS, 256>>>(x, gate_w, e1_w, sh1_w, e2_w, sh2_w, out);

    topk_route_kernel<<<TOK / 8, 256>>>();
    finalize_kernel<<<1, 64>>>(out);

    // GEMM1: experts (gather tok -> h) + shared (x -> shh)
    mgemm<1, 0, 1, 0><<<dim3(TOK / 128, HH / 128, EE + 1), 256, TG_SMEM>>>(
        p_x_hi, p_x_lo, p_e1h, p_e1l, e1_b, p_tok,
        nullptr, p_h_hi, p_h_lo,
        p_x_hi, p_x_lo, p_s1h, p_s1l, sh1_b,
        nullptr, p_shh_hi, p_shh_lo,
        DD, HH, HH, DD);

    // GEMM2: experts + shared; fused combine via atomicAdd into out
    mgemm<0, 1, 0, 1><<<dim3(TOK / 128, DD / 128, EE + 1), 256, TG_SMEM>>>(
        p_h_hi, p_h_lo, p_e2h, p_e2l, e2_b, p_pair,
        out, nullptr, nullptr,
        p_shh_hi, p_shh_lo, p_s2h, p_s2l, sh2_b,
        out, nullptr, nullptr,
        HH, DD, DD, HH);
}

// round 15
// speedup vs baseline: 1.0294x; 1.0078x over previous
#include <cuda_runtime.h>
#include <cuda_bf16.h>
#include <math.h>
#include <stdint.h>

// ---------------- problem constants ----------------
static constexpr int TOK   = 4096;
static constexpr int DD    = 768;
static constexpr int HH    = 1536;
static constexpr int EE    = 64;
static constexpr int TOPK  = 6;
static constexpr int CAP   = 1536;
static constexpr int NPAIR = TOK * TOPK;
static constexpr int OUT_MAIN = TOK * DD;

#define FULLMASK 0xFFFFFFFFu

// ---------------- scratch ----------------
__device__ float g_logits[TOK * EE];
__device__ float g_prob_sum[EE];
__device__ int   g_counts[EE];
__device__ int   g_tok[EE * CAP];
__device__ int   g_pairidx[EE * CAP];
__device__ float g_score[EE * CAP];
__device__ int   g_ident[TOK];
__device__ float g_ones[TOK];
__device__ __nv_bfloat16 g_x_hi[(size_t)TOK * DD];
__device__ __nv_bfloat16 g_x_lo[(size_t)TOK * DD];
__device__ __nv_bfloat16 g_s1w_hi[(size_t)HH * DD];
__device__ __nv_bfloat16 g_s1w_lo[(size_t)HH * DD];
__device__ __nv_bfloat16 g_s2w_hi[(size_t)DD * HH];
__device__ __nv_bfloat16 g_s2w_lo[(size_t)DD * HH];
__device__ __nv_bfloat16 g_e1w_hi[(size_t)EE * HH * DD];
__device__ __nv_bfloat16 g_e1w_lo[(size_t)EE * HH * DD];
__device__ __nv_bfloat16 g_e2w_hi[(size_t)EE * DD * HH];
__device__ __nv_bfloat16 g_e2w_lo[(size_t)EE * DD * HH];
__device__ __nv_bfloat16 g_shh_hi[(size_t)TOK * HH];
__device__ __nv_bfloat16 g_shh_lo[(size_t)TOK * HH];
__device__ __nv_bfloat16 g_h_hi[(size_t)NPAIR * HH];
__device__ __nv_bfloat16 g_h_lo[(size_t)NPAIR * HH];

static constexpr int XS_N8 = TOK * DD / 8;
static constexpr int S1_N8 = HH * DD / 8;
static constexpr int S2_N8 = DD * HH / 8;
static constexpr int E1_N8 = EE * HH * DD / 8;
static constexpr int E2_N8 = EE * DD * HH / 8;

// ---------------- helpers ----------------
__device__ __forceinline__ uint32_t smem_u32(const void* p) {
    uint32_t a;
    asm("{ .reg .u64 t; cvta.to.shared.u64 t, %1; cvt.u32.u64 %0, t; }" : "=r"(a) : "l"(p));
    return a;
}
__device__ __forceinline__ uint32_t cvt_bf2(float hi_upper, float lo_lower) {
    uint32_t r;
    asm("cvt.rn.bf16x2.f32 %0, %1, %2;" : "=r"(r) : "f"(hi_upper), "f"(lo_lower));
    return r;
}
__device__ __forceinline__ void split2(float v0, float v1, uint32_t& h, uint32_t& l) {
    h = cvt_bf2(v1, v0);
    float f0 = __uint_as_float(h << 16);
    float f1 = __uint_as_float(h & 0xffff0000u);
    l = cvt_bf2(v1 - f1, v0 - f0);
}
__device__ __forceinline__ void split_one(const float* __restrict__ src,
                                          __nv_bfloat16* __restrict__ hi,
                                          __nv_bfloat16* __restrict__ lo, int i) {
    const float4* s = (const float4*)src + (size_t)i * 2;
    float4 v0 = s[0], v1 = s[1];
    uint32_t h0, l0, h1, l1, h2, l2, h3, l3;
    split2(v0.x, v0.y, h0, l0);
    split2(v0.z, v0.w, h1, l1);
    split2(v1.x, v1.y, h2, l2);
    split2(v1.z, v1.w, h3, l3);
    ((uint4*)hi)[i] = make_uint4(h0, h1, h2, h3);
    ((uint4*)lo)[i] = make_uint4(l0, l1, l2, l3);
}
__device__ __forceinline__ float gelu_ex(float x) {
    return 0.5f * x * (1.0f + erff(x * 0.70710678118654752f));
}
__device__ __forceinline__ void hmma(float* c, const uint32_t* a, uint32_t b0, uint32_t b1) {
    asm volatile(
        "mma.sync.aligned.m16n8k16.row.col.f32.bf16.bf16.f32 "
        "{%0,%1,%2,%3}, {%4,%5,%6,%7}, {%8,%9}, {%0,%1,%2,%3};"
        : "+f"(c[0]), "+f"(c[1]), "+f"(c[2]), "+f"(c[3])
        : "r"(a[0]), "r"(a[1]), "r"(a[2]), "r"(a[3]), "r"(b0), "r"(b1));
}
#define LDSM4(r, a) \
    asm volatile("ldmatrix.sync.aligned.m8n8.x4.shared.b16 {%0,%1,%2,%3}, [%4];" \
                 : "=r"((r)[0]), "=r"((r)[1]), "=r"((r)[2]), "=r"((r)[3]) : "r"(a))
__device__ __forceinline__ void cpa16(uint32_t dst, const void* src, uint32_t srcsz) {
    asm volatile("cp.async.cg.shared.global [%0], [%1], 16, %2;"
                 :: "r"(dst), "l"(src), "r"(srcsz));
}
#define CP_COMMIT() asm volatile("cp.async.commit_group;" ::: "memory")
#define CP_WAIT1()  asm volatile("cp.async.wait_group 1;" ::: "memory")

__device__ __forceinline__ unsigned long long ffma2(unsigned long long a,
                                                    unsigned long long b,
                                                    unsigned long long c) {
    unsigned long long d;
    asm("fma.rn.f32x2 %0, %1, %2, %3;" : "=l"(d) : "l"(a), "l"(b), "l"(c));
    return d;
}
__device__ __forceinline__ unsigned long long pack2f(float x) {
    unsigned long long d;
    asm("mov.b64 %0, {%1, %1};" : "=l"(d) : "f"(x));
    return d;
}
__device__ __forceinline__ float2 unpack2f(unsigned long long v) {
    float2 r;
    asm("mov.b64 {%0, %1}, %2;" : "=f"(r.x), "=f"(r.y) : "l"(v));
    return r;
}

// ---------------- fused prep (R11-exact) ----------------
static constexpr int GATE_BLKS = 64;
static constexpr int XS_B = XS_N8 / 256;
static constexpr int E1_B = E1_N8 / 256;
static constexpr int S1_B = S1_N8 / 256;
static constexpr int E2_B = E2_N8 / 256;
static constexpr int S2_B = S2_N8 / 256;
static constexpr int ZO_B = TOK * DD / 4 / 256;
static constexpr int RS_B = TOK / 256;
static constexpr int PREP_BLKS =
    GATE_BLKS + XS_B + E1_B + S1_B + E2_B + S2_B + ZO_B + RS_B;

__global__ __launch_bounds__(256) void prep_kernel(
    const float* __restrict__ x, const float* __restrict__ gate_w,
    const float* __restrict__ e1_w, const float* __restrict__ sh1_w,
    const float* __restrict__ e2_w, const float* __restrict__ sh2_w,
    float* __restrict__ out) {
    int bx = blockIdx.x;
    int tid = threadIdx.x;
    if (bx < GATE_BLKS) {
        constexpr int BM = 64, BN = 64, BK = 16, TM = 4, TN = 4;
        __shared__ __align__(16) float As[BK][BM + 4];
        __shared__ __align__(16) float Bs[BK][BN + 4];
        int m0 = bx * BM;
        int tx = tid % (BN / TN), ty = tid / (BN / TN);
        int mb = ty * TM, nb = tx * TN;
        unsigned long long acc[TM / 2][TN];
#pragma unroll
        for (int i = 0; i < TM / 2; i++)
#pragma unroll
            for (int j = 0; j < TN; j++) acc[i][j] = 0ull;
        for (int kk = 0; kk < DD; kk += BK) {
#pragma unroll
            for (int it = 0; it < BM * BK / 4; it += 256) {
                int i = it + tid;
                int m = i / (BK / 4), k4 = (i % (BK / 4)) * 4;
                float4 v = *(const float4*)(x + (size_t)(m0 + m) * DD + kk + k4);
                As[k4 + 0][m] = v.x; As[k4 + 1][m] = v.y;
                As[k4 + 2][m] = v.z; As[k4 + 3][m] = v.w;
            }
#pragma unroll
            for (int it = 0; it < BN * BK / 4; it += 256) {
                int i = it + tid;
                int n = i / (BK / 4), k4 = (i % (BK / 4)) * 4;
                float4 v = *(const float4*)(gate_w + (size_t)n * DD + kk + k4);
                Bs[k4 + 0][n] = v.x; Bs[k4 + 1][n] = v.y;
                Bs[k4 + 2][n] = v.z; Bs[k4 + 3][n] = v.w;
            }
            __syncthreads();
#pragma unroll
            for (int k = 0; k < BK; k++) {
                unsigned long long a2[TM / 2];
                ulonglong2 av = *(const ulonglong2*)&As[k][mb];
                a2[0] = av.x; a2[1] = av.y;
                float4 b4 = *(const float4*)&Bs[k][nb];
                float bv[4] = {b4.x, b4.y, b4.z, b4.w};
#pragma unroll
                for (int j = 0; j < TN; j++) {
                    unsigned long long b2 = pack2f(bv[j]);
#pragma unroll
                    for (int i = 0; i < TM / 2; i++) acc[i][j] = ffma2(a2[i], b2, acc[i][j]);
                }
            }
            __syncthreads();
        }
#pragma unroll
        for (int i = 0; i < TM / 2; i++)
#pragma unroll
            for (int j = 0; j < TN; j++) {
                float2 u = unpack2f(acc[i][j]);
                g_logits[(size_t)(m0 + mb + 2 * i) * EE + nb + j] = u.x;
                g_logits[(size_t)(m0 + mb + 2 * i + 1) * EE + nb + j] = u.y;
            }
        return;
    }
    bx -= GATE_BLKS;
    if (bx < XS_B) { split_one(x, g_x_hi, g_x_lo, bx * 256 + tid); return; }
    bx -= XS_B;
    if (bx < E1_B) { split_one(e1_w, g_e1w_hi, g_e1w_lo, bx * 256 + tid); return; }
    bx -= E1_B;
    if (bx < S1_B) { split_one(sh1_w, g_s1w_hi, g_s1w_lo, bx * 256 + tid); return; }
    bx -= S1_B;
    if (bx < E2_B) { split_one(e2_w, g_e2w_hi, g_e2w_lo, bx * 256 + tid); return; }
    bx -= E2_B;
    if (bx < S2_B) { split_one(sh2_w, g_s2w_hi, g_s2w_lo, bx * 256 + tid); return; }
    bx -= S2_B;
    if (bx < ZO_B) {
        ((float4*)out)[bx * 256 + tid] = make_float4(0.f, 0.f, 0.f, 0.f);
        return;
    }
    bx -= ZO_B;
    int i = bx * 256 + tid;
    g_ident[i] = i;
    g_ones[i] = 1.0f;
    if (i < EE) { g_counts[i] = 0; g_prob_sum[i] = 0.0f; }
}

// ---------------- 2-CTA/SM GEMM, 4 warps/CTA, warp tile 64x64 ----------------
// BM=128, BN=128, BK=32; 128 threads (2x2 warp grid); hi/lo packed per 128B row.
// Stage = 32KB; 2 stages; 2 CTAs/SM; HMMA/LDSM ratio 6 (as R11).
static constexpr int TG_BM = 128, TG_BN = 128, TG_BK = 32;
static constexpr int STG_B  = 16384;
static constexpr int STG_SZ = 32768;
static constexpr int TG_SMEM = 1024 + 2 * STG_SZ;   // 66560

template <int ACT, int SCALE, int CBF, int ATOMIC>
__global__ __launch_bounds__(128, 2) void mgemm(
    // expert side
    const __nv_bfloat16* __restrict__ Ah_e, const __nv_bfloat16* __restrict__ Al_e,
    const __nv_bfloat16* __restrict__ We_h, const __nv_bfloat16* __restrict__ We_l,
    const float* __restrict__ bias_e,
    const int* __restrict__ aidx_e,
    float* __restrict__ Cf_e, __nv_bfloat16* __restrict__ Ch_e, __nv_bfloat16* __restrict__ Cl_e,
    // shared side
    const __nv_bfloat16* __restrict__ Ah_s, const __nv_bfloat16* __restrict__ Al_s,
    const __nv_bfloat16* __restrict__ Ws_h, const __nv_bfloat16* __restrict__ Ws_l,
    const float* __restrict__ bias_s,
    float* __restrict__ Cf_s, __nv_bfloat16* __restrict__ Ch_s, __nv_bfloat16* __restrict__ Cl_s,
    int lda, int ldc, int N, int K) {
    const int z = blockIdx.z;
    const bool isSh = (z == EE);
    int M;
    const __nv_bfloat16 *Ah, *Al, *Wh, *Wl;
    const float *biasp, *rsp;
    const int *aidxp, *cidxp;
    float* Cf;
    __nv_bfloat16 *Ch, *Cl;
    if (isSh) {
        M = TOK;
        Ah = Ah_s; Al = Al_s; Wh = Ws_h; Wl = Ws_l; biasp = bias_s;
        aidxp = g_ident; cidxp = g_ident; rsp = g_ones;
        Cf = Cf_s; Ch = Ch_s; Cl = Cl_s;
    } else {
        int c = g_counts[z];
        M = c < CAP ? c : CAP;
        Ah = Ah_e; Al = Al_e;
        Wh = We_h + (size_t)z * N * K; Wl = We_l + (size_t)z * N * K;
        biasp = bias_e + (size_t)z * N;
        aidxp = aidx_e + z * CAP; cidxp = g_pairidx + z * CAP; rsp = g_score + z * CAP;
        Cf = Cf_e; Ch = Ch_e; Cl = Cl_e;
    }
    int m0 = blockIdx.x * TG_BM;
    if (m0 >= M) return;
    int n0 = blockIdx.y * TG_BN;

    extern __shared__ char smem_raw[];
    uint32_t sb = smem_u32(smem_raw);
    uint32_t tiles = (sb + 1023u) & ~1023u;

    const int tid = threadIdx.x;
    const int lane = tid & 31;
    const int w = tid >> 5;                     // 0..3
    const int wm = w & 1, wn = w >> 1;          // 2x2 warp grid, 64x64 tiles

    // ---- cp.async fill geometry: 128 threads, 8 chunks each per matrix ----
    const int c8 = tid & 7;
    const int r0 = tid >> 3;                    // 0..15
    const bool isHi = c8 < 4;
    const int kcol = (c8 & 3) * 8;
    const uint32_t offBase = (uint32_t)(r0 * 128 + ((c8 ^ (r0 & 7)) << 4));
    const char* aSrc[8];
    uint32_t aSz[8];
#pragma unroll
    for (int i = 0; i < 8; i++) {
        int gm = m0 + r0 + 16 * i;
        bool v = gm < M;
        int ar = v ? aidxp[gm] : 0;
        const __nv_bfloat16* base = isHi ? Ah : Al;
        aSrc[i] = (const char*)(base + (size_t)ar * lda + kcol);
        aSz[i] = v ? 16u : 0u;
    }
    const char* bSrc = (const char*)((isHi ? Wh : Wl) + (size_t)(n0 + r0) * K + kcol);

#define FILL(kk, buf)                                                             \
    {                                                                             \
        uint32_t sg = tiles + (uint32_t)(buf) * STG_SZ;                           \
        _Pragma("unroll")                                                         \
        for (int i = 0; i < 8; i++)                                               \
            cpa16(sg + offBase + i * 2048, aSrc[i] + (size_t)(kk) * 2, aSz[i]);   \
        _Pragma("unroll")                                                         \
        for (int i = 0; i < 8; i++)                                               \
            cpa16(sg + STG_B + offBase + i * 2048,                                \
                  bSrc + (size_t)(kk) * 2 + (size_t)i * 16 * K * 2, 16);          \
    }

    // ---- ldmatrix per-lane geometry ----
    const int arow16 = (lane & 7) | (lane & 8);
    const uint32_t ak = (lane & 16) ? 1u : 0u;
    const int brow16 = (lane & 7) | ((lane & 16) >> 1);
    const uint32_t bk = (lane & 8) ? 1u : 0u;
    uint32_t artA[4], artB[4];
#pragma unroll
    for (int mi = 0; mi < 4; mi++) {
        int row = wm * 64 + mi * 16 + arow16;
        artA[mi] = (uint32_t)(row * 128) | ((uint32_t)(row & 7) << 4);
    }
#pragma unroll
    for (int nj = 0; nj < 4; nj++) {
        int row = wn * 64 + nj * 16 + brow16;
        artB[nj] = (uint32_t)(row * 128) | ((uint32_t)(row & 7) << 4);
    }

    float acc[4][8][4];
#pragma unroll
    for (int i = 0; i < 4; i++)
#pragma unroll
        for (int j = 0; j < 8; j++)
#pragma unroll
            for (int q = 0; q < 4; q++) acc[i][j][q] = 0.0f;

    const int KT = K / TG_BK;

    FILL(0, 0);
    CP_COMMIT();
    FILL(TG_BK, 1);
    CP_COMMIT();

    for (int t = 0; t < KT; t++) {
        CP_WAIT1();
        __syncthreads();
        const uint32_t sgA = tiles + (uint32_t)(t & 1) * STG_SZ;
        const uint32_t sgB = sgA + STG_B;
#pragma unroll
        for (int ks = 0; ks < 2; ks++) {
            const uint32_t cA = (uint32_t)(ks * 2) + ak;
            uint32_t ahf[4][4], alf[4][4];
#pragma unroll
            for (int mi = 0; mi < 4; mi++) {
                LDSM4(ahf[mi], sgA + (artA[mi] ^ (cA << 4)));
                LDSM4(alf[mi], sgA + (artA[mi] ^ ((cA + 4) << 4)));
            }
            const uint32_t cB = (uint32_t)(ks * 2) + bk;
#pragma unroll
            for (int nj = 0; nj < 4; nj++) {
                uint32_t bh[4], bl[4];
                LDSM4(bh, sgB + (artB[nj] ^ (cB << 4)));
                LDSM4(bl, sgB + (artB[nj] ^ ((cB + 4) << 4)));
#pragma unroll
                for (int mi = 0; mi < 4; mi++) {
                    hmma(acc[mi][2 * nj],     ahf[mi], bh[0], bh[1]);
                    hmma(acc[mi][2 * nj + 1], ahf[mi], bh[2], bh[3]);
                }
#pragma unroll
                for (int mi = 0; mi < 4; mi++) {
                    hmma(acc[mi][2 * nj],     ahf[mi], bl[0], bl[1]);
                    hmma(acc[mi][2 * nj + 1], ahf[mi], bl[2], bl[3]);
                }
#pragma unroll
                for (int mi = 0; mi < 4; mi++) {
                    hmma(acc[mi][2 * nj],     alf[mi], bh[0], bh[1]);
                    hmma(acc[mi][2 * nj + 1], alf[mi], bh[2], bh[3]);
                }
            }
        }
        __syncthreads();
        if (t + 2 < KT) FILL((t + 2) * TG_BK, t & 1);
        CP_COMMIT();
    }
#undef FILL

    // ---- epilogue ----
    const int g = lane >> 2, q2 = (lane & 3) * 2;
#pragma unroll
    for (int mi = 0; mi < 4; mi++) {
        int ml = m0 + wm * 64 + mi * 16 + g;
        int mh = ml + 8;
        bool vlo = ml < M, vhi = mh < M;
        int cr0 = 0, cr1 = 0;
        float s0 = 1.0f, s1 = 1.0f;
        if (vlo) { cr0 = cidxp[ml]; if (SCALE) s0 = rsp[ml]; }
        if (vhi) { cr1 = cidxp[mh]; if (SCALE) s1 = rsp[mh]; }
        if (ATOMIC) {
            if (vlo && !isSh) cr0 = cr0 / TOPK;
            if (vhi && !isSh) cr1 = cr1 / TOPK;
        }
#pragma unroll
        for (int nf = 0; nf < 8; nf++) {
            int gn = n0 + wn * 64 + nf * 8 + q2;
            float b0 = biasp[gn], b1 = biasp[gn + 1];
            float v0 = acc[mi][nf][0] + b0, v1 = acc[mi][nf][1] + b1;
            float v2 = acc[mi][nf][2] + b0, v3 = acc[mi][nf][3] + b1;
            if (ACT) { v0 = gelu_ex(v0); v1 = gelu_ex(v1); v2 = gelu_ex(v2); v3 = gelu_ex(v3); }
            if (SCALE) { v0 *= s0; v1 *= s0; v2 *= s1; v3 *= s1; }
            if (!CBF) {
                if (ATOMIC) {
                    if (vlo) {
                        float* p = Cf + (size_t)cr0 * ldc + gn;
                        atomicAdd(p, v0); atomicAdd(p + 1, v1);
                    }
                    if (vhi) {
                        float* p = Cf + (size_t)cr1 * ldc + gn;
                        atomicAdd(p, v2); atomicAdd(p + 1, v3);
                    }
                } else {
                    if (vlo) *(float2*)(Cf + (size_t)cr0 * ldc + gn) = make_float2(v0, v1);
                    if (vhi) *(float2*)(Cf + (size_t)cr1 * ldc + gn) = make_float2(v2, v3);
                }
            } else {
                if (vlo) {
                    uint32_t h, l;
                    split2(v0, v1, h, l);
                    *(uint32_t*)(Ch + (size_t)cr0 * ldc + gn) = h;
                    *(uint32_t*)(Cl + (size_t)cr0 * ldc + gn) = l;
                }
                if (vhi) {
                    uint32_t h, l;
                    split2(v2, v3, h, l);
                    *(uint32_t*)(Ch + (size_t)cr1 * ldc + gn) = h;
                    *(uint32_t*)(Cl + (size_t)cr1 * ldc + gn) = l;
                }
            }
        }
    }
}

// ---------------- softmax + top-k + routing + prob accumulation ----------------
__global__ void topk_route_kernel() {
    int gw = (blockIdx.x * blockDim.x + threadIdx.x) >> 5;
    int lane = threadIdx.x & 31;
    if (gw >= TOK) return;
    float2 v = ((const float2*)(g_logits + (size_t)gw * EE))[lane];
    float m = fmaxf(v.x, v.y);
#pragma unroll
    for (int o = 16; o > 0; o >>= 1) m = fmaxf(m, __shfl_xor_sync(FULLMASK, m, o));
    float e0 = __expf(v.x - m), e1 = __expf(v.y - m);
    float s = e0 + e1;
#pragma unroll
    for (int o = 16; o > 0; o >>= 1) s += __shfl_xor_sync(FULLMASK, s, o);
    float inv = 1.0f / s;
    float p0 = e0 * inv, p1 = e1 * inv;
    atomicAdd(&g_prob_sum[2 * lane], p0);
    atomicAdd(&g_prob_sum[2 * lane + 1], p1);

    float a0 = p0, a1 = p1;
    for (int k = 0; k < TOPK; k++) {
        float bvv; int bi;
        if (a0 >= a1) { bvv = a0; bi = 2 * lane; }
        else          { bvv = a1; bi = 2 * lane + 1; }
#pragma unroll
        for (int o = 16; o > 0; o >>= 1) {
            float ov = __shfl_xor_sync(FULLMASK, bvv, o);
            int oi = __shfl_xor_sync(FULLMASK, bi, o);
            if (ov > bvv || (ov == bvv && oi < bi)) { bvv = ov; bi = oi; }
        }
        if ((bi >> 1) == lane) {
            if (bi & 1) a1 = -1.0f; else a0 = -1.0f;
            int slot = atomicAdd(&g_counts[bi], 1);
            if (slot < CAP) {
                int base = bi * CAP + slot;
                g_tok[base] = gw;
                g_pairidx[base] = gw * TOPK + k;
                g_score[base] = bvv;
            }
        }
    }
}

// ---------------- scalar outputs ----------------
__global__ void finalize_kernel(float* __restrict__ out) {
    __shared__ float sh[EE];
    int e = threadIdx.x;
    float freq = (float)g_counts[e] / (float)(TOK * TOPK);
    float prob = g_prob_sum[e] * (1.0f / (float)TOK);
    out[OUT_MAIN + 1 + e] = freq;
    out[OUT_MAIN + 1 + EE + e] = prob;
    sh[e] = freq * prob;
    __syncthreads();
    if (e == 0) {
        float s = 0.0f;
        for (int i = 0; i < EE; i++) s += sh[i];
        out[OUT_MAIN] = 0.01f * s;
    }
}

// ---------------- launch ----------------
extern "C" void kernel_launch(void* const* d_in, const int* in_sizes, int n_in,
                              void* d_out, int out_size) {
    const float* x      = (const float*)d_in[0];
    const float* gate_w = (const float*)d_in[1];
    const float* sh1_w  = (const float*)d_in[2];
    const float* sh1_b  = (const float*)d_in[3];
    const float* sh2_w  = (const float*)d_in[4];
    const float* sh2_b  = (const float*)d_in[5];
    const float* e1_w   = (const float*)d_in[6];
    const float* e1_b   = (const float*)d_in[7];
    const float* e2_w   = (const float*)d_in[8];
    const float* e2_b   = (const float*)d_in[9];
    float* out = (float*)d_out;

    int *p_tok, *p_pair;
    __nv_bfloat16 *p_x_hi, *p_x_lo, *p_s1h, *p_s1l, *p_s2h, *p_s2l;
    __nv_bfloat16 *p_e1h, *p_e1l, *p_e2h, *p_e2l;
    __nv_bfloat16 *p_shh_hi, *p_shh_lo, *p_h_hi, *p_h_lo;
    cudaGetSymbolAddress((void**)&p_tok, g_tok);
    cudaGetSymbolAddress((void**)&p_pair, g_pairidx);
    cudaGetSymbolAddress((void**)&p_x_hi, g_x_hi);
    cudaGetSymbolAddress((void**)&p_x_lo, g_x_lo);
    cudaGetSymbolAddress((void**)&p_s1h, g_s1w_hi);
    cudaGetSymbolAddress((void**)&p_s1l, g_s1w_lo);
    cudaGetSymbolAddress((void**)&p_s2h, g_s2w_hi);
    cudaGetSymbolAddress((void**)&p_s2l, g_s2w_lo);
    cudaGetSymbolAddress((void**)&p_e1h, g_e1w_hi);
    cudaGetSymbolAddress((void**)&p_e1l, g_e1w_lo);
    cudaGetSymbolAddress((void**)&p_e2h, g_e2w_hi);
    cudaGetSymbolAddress((void**)&p_e2l, g_e2w_lo);
    cudaGetSymbolAddress((void**)&p_shh_hi, g_shh_hi);
    cudaGetSymbolAddress((void**)&p_shh_lo, g_shh_lo);
    cudaGetSymbolAddress((void**)&p_h_hi, g_h_hi);
    cudaGetSymbolAddress((void**)&p_h_lo, g_h_lo);

    cudaFuncSetAttribute(mgemm<1, 0, 1, 0>,
                         cudaFuncAttributeMaxDynamicSharedMemorySize, TG_SMEM);
    cudaFuncSetAttribute(mgemm<0, 1, 0, 1>,
                         cudaFuncAttributeMaxDynamicSharedMemorySize, TG_SMEM);

    // fused prep (R11-exact)
    prep_kernel<<<PREP_BLKS, 256>>>(x, gate_w, e1_w, sh1_w, e2_w, sh2_w, out);

    topk_route_kernel<<<TOK / 8, 256>>>();
    finalize_kernel<<<1, 64>>>(out);

    // GEMM1: experts (gather tok -> h) + shared (x -> shh)
    mgemm<1, 0, 1, 0><<<dim3(TOK / 128, HH / 128, EE + 1), 128, TG_SMEM>>>(
        p_x_hi, p_x_lo, p_e1h, p_e1l, e1_b, p_tok,
        nullptr, p_h_hi, p_h_lo,
        p_x_hi, p_x_lo, p_s1h, p_s1l, sh1_b,
        nullptr, p_shh_hi, p_shh_lo,
        DD, HH, HH, DD);

    // GEMM2: experts + shared; fused combine via atomicAdd into out
    mgemm<0, 1, 0, 1><<<dim3(TOK / 128, DD / 128, EE + 1), 128, TG_SMEM>>>(
        p_h_hi, p_h_lo, p_e2h, p_e2l, e2_b, p_pair,
        out, nullptr, nullptr,
        p_shh_hi, p_shh_lo, p_s2h, p_s2l, sh2_b,
        out, nullptr, nullptr,
        HH, DD, DD, HH);
}

// round 16
// speedup vs baseline: 1.0403x; 1.0105x over previous
#include <cuda_runtime.h>
#include <cuda_bf16.h>
#include <math.h>
#include <stdint.h>

// ---------------- problem constants ----------------
static constexpr int TOK   = 4096;
static constexpr int DD    = 768;
static constexpr int HH    = 1536;
static constexpr int EE    = 64;
static constexpr int TOPK  = 6;
static constexpr int CAP   = 1536;
static constexpr int NPAIR = TOK * TOPK;
static constexpr int OUT_MAIN = TOK * DD;

#define FULLMASK 0xFFFFFFFFu

// ---------------- scratch ----------------
__device__ float g_logits[TOK * EE];
__device__ float g_prob_sum[EE];
__device__ int   g_counts[EE];
__device__ int   g_tok[EE * CAP];
__device__ int   g_pairidx[EE * CAP];
__device__ float g_score[EE * CAP];
__device__ int   g_ident[TOK];
__device__ float g_ones[TOK];
__device__ __nv_bfloat16 g_x_hi[(size_t)TOK * DD];
__device__ __nv_bfloat16 g_x_lo[(size_t)TOK * DD];
__device__ __nv_bfloat16 g_s1w_hi[(size_t)HH * DD];
__device__ __nv_bfloat16 g_s1w_lo[(size_t)HH * DD];
__device__ __nv_bfloat16 g_s2w_hi[(size_t)DD * HH];
__device__ __nv_bfloat16 g_s2w_lo[(size_t)DD * HH];
__device__ __nv_bfloat16 g_e1w_hi[(size_t)EE * HH * DD];
__device__ __nv_bfloat16 g_e1w_lo[(size_t)EE * HH * DD];
__device__ __nv_bfloat16 g_e2w_hi[(size_t)EE * DD * HH];
__device__ __nv_bfloat16 g_e2w_lo[(size_t)EE * DD * HH];
__device__ __nv_bfloat16 g_shh_hi[(size_t)TOK * HH];
__device__ __nv_bfloat16 g_shh_lo[(size_t)TOK * HH];
__device__ __nv_bfloat16 g_h_hi[(size_t)NPAIR * HH];
__device__ __nv_bfloat16 g_h_lo[(size_t)NPAIR * HH];

static constexpr int XS_N8 = TOK * DD / 8;
static constexpr int S1_N8 = HH * DD / 8;
static constexpr int S2_N8 = DD * HH / 8;
static constexpr int E1_N8 = EE * HH * DD / 8;
static constexpr int E2_N8 = EE * DD * HH / 8;

// ---------------- helpers ----------------
__device__ __forceinline__ uint32_t smem_u32(const void* p) {
    uint32_t a;
    asm("{ .reg .u64 t; cvta.to.shared.u64 t, %1; cvt.u32.u64 %0, t; }" : "=r"(a) : "l"(p));
    return a;
}
__device__ __forceinline__ uint32_t cvt_bf2(float hi_upper, float lo_lower) {
    uint32_t r;
    asm("cvt.rn.bf16x2.f32 %0, %1, %2;" : "=r"(r) : "f"(hi_upper), "f"(lo_lower));
    return r;
}
__device__ __forceinline__ void split2(float v0, float v1, uint32_t& h, uint32_t& l) {
    h = cvt_bf2(v1, v0);
    float f0 = __uint_as_float(h << 16);
    float f1 = __uint_as_float(h & 0xffff0000u);
    l = cvt_bf2(v1 - f1, v0 - f0);
}
__device__ __forceinline__ void split_one(const float* __restrict__ src,
                                          __nv_bfloat16* __restrict__ hi,
                                          __nv_bfloat16* __restrict__ lo, int i) {
    const float4* s = (const float4*)src + (size_t)i * 2;
    float4 v0 = s[0], v1 = s[1];
    uint32_t h0, l0, h1, l1, h2, l2, h3, l3;
    split2(v0.x, v0.y, h0, l0);
    split2(v0.z, v0.w, h1, l1);
    split2(v1.x, v1.y, h2, l2);
    split2(v1.z, v1.w, h3, l3);
    ((uint4*)hi)[i] = make_uint4(h0, h1, h2, h3);
    ((uint4*)lo)[i] = make_uint4(l0, l1, l2, l3);
}
__device__ __forceinline__ float gelu_ex(float x) {
    return 0.5f * x * (1.0f + erff(x * 0.70710678118654752f));
}
__device__ __forceinline__ void hmma(float* c, const uint32_t* a, uint32_t b0, uint32_t b1) {
    asm volatile(
        "mma.sync.aligned.m16n8k16.row.col.f32.bf16.bf16.f32 "
        "{%0,%1,%2,%3}, {%4,%5,%6,%7}, {%8,%9}, {%0,%1,%2,%3};"
        : "+f"(c[0]), "+f"(c[1]), "+f"(c[2]), "+f"(c[3])
        : "r"(a[0]), "r"(a[1]), "r"(a[2]), "r"(a[3]), "r"(b0), "r"(b1));
}
#define LDSM4(r, a) \
    asm volatile("ldmatrix.sync.aligned.m8n8.x4.shared.b16 {%0,%1,%2,%3}, [%4];" \
                 : "=r"((r)[0]), "=r"((r)[1]), "=r"((r)[2]), "=r"((r)[3]) : "r"(a))
__device__ __forceinline__ void cpa16(uint32_t dst, const void* src, uint32_t srcsz) {
    asm volatile("cp.async.cg.shared.global [%0], [%1], 16, %2;"
                 :: "r"(dst), "l"(src), "r"(srcsz));
}
#define CP_COMMIT() asm volatile("cp.async.commit_group;" ::: "memory")
#define CP_WAIT1()  asm volatile("cp.async.wait_group 1;" ::: "memory")

__device__ __forceinline__ unsigned long long ffma2(unsigned long long a,
                                                    unsigned long long b,
                                                    unsigned long long c) {
    unsigned long long d;
    asm("fma.rn.f32x2 %0, %1, %2, %3;" : "=l"(d) : "l"(a), "l"(b), "l"(c));
    return d;
}
__device__ __forceinline__ unsigned long long pack2f(float x) {
    unsigned long long d;
    asm("mov.b64 %0, {%1, %1};" : "=l"(d) : "f"(x));
    return d;
}
__device__ __forceinline__ float2 unpack2f(unsigned long long v) {
    float2 r;
    asm("mov.b64 {%0, %1}, %2;" : "=f"(r.x), "=f"(r.y) : "l"(v));
    return r;
}

// ---------------- fused prep (R11-exact) ----------------
static constexpr int GATE_BLKS = 64;
static constexpr int XS_B = XS_N8 / 256;
static constexpr int E1_B = E1_N8 / 256;
static constexpr int S1_B = S1_N8 / 256;
static constexpr int E2_B = E2_N8 / 256;
static constexpr int S2_B = S2_N8 / 256;
static constexpr int ZO_B = TOK * DD / 4 / 256;
static constexpr int RS_B = TOK / 256;
static constexpr int PREP_BLKS =
    GATE_BLKS + XS_B + E1_B + S1_B + E2_B + S2_B + ZO_B + RS_B;

__global__ __launch_bounds__(256) void prep_kernel(
    const float* __restrict__ x, const float* __restrict__ gate_w,
    const float* __restrict__ e1_w, const float* __restrict__ sh1_w,
    const float* __restrict__ e2_w, const float* __restrict__ sh2_w,
    float* __restrict__ out) {
    int bx = blockIdx.x;
    int tid = threadIdx.x;
    if (bx < GATE_BLKS) {
        constexpr int BM = 64, BN = 64, BK = 16, TM = 4, TN = 4;
        __shared__ __align__(16) float As[BK][BM + 4];
        __shared__ __align__(16) float Bs[BK][BN + 4];
        int m0 = bx * BM;
        int tx = tid % (BN / TN), ty = tid / (BN / TN);
        int mb = ty * TM, nb = tx * TN;
        unsigned long long acc[TM / 2][TN];
#pragma unroll
        for (int i = 0; i < TM / 2; i++)
#pragma unroll
            for (int j = 0; j < TN; j++) acc[i][j] = 0ull;
        for (int kk = 0; kk < DD; kk += BK) {
#pragma unroll
            for (int it = 0; it < BM * BK / 4; it += 256) {
                int i = it + tid;
                int m = i / (BK / 4), k4 = (i % (BK / 4)) * 4;
                float4 v = *(const float4*)(x + (size_t)(m0 + m) * DD + kk + k4);
                As[k4 + 0][m] = v.x; As[k4 + 1][m] = v.y;
                As[k4 + 2][m] = v.z; As[k4 + 3][m] = v.w;
            }
#pragma unroll
            for (int it = 0; it < BN * BK / 4; it += 256) {
                int i = it + tid;
                int n = i / (BK / 4), k4 = (i % (BK / 4)) * 4;
                float4 v = *(const float4*)(gate_w + (size_t)n * DD + kk + k4);
                Bs[k4 + 0][n] = v.x; Bs[k4 + 1][n] = v.y;
                Bs[k4 + 2][n] = v.z; Bs[k4 + 3][n] = v.w;
            }
            __syncthreads();
#pragma unroll
            for (int k = 0; k < BK; k++) {
                unsigned long long a2[TM / 2];
                ulonglong2 av = *(const ulonglong2*)&As[k][mb];
                a2[0] = av.x; a2[1] = av.y;
                float4 b4 = *(const float4*)&Bs[k][nb];
                float bv[4] = {b4.x, b4.y, b4.z, b4.w};
#pragma unroll
                for (int j = 0; j < TN; j++) {
                    unsigned long long b2 = pack2f(bv[j]);
#pragma unroll
                    for (int i = 0; i < TM / 2; i++) acc[i][j] = ffma2(a2[i], b2, acc[i][j]);
                }
            }
            __syncthreads();
        }
#pragma unroll
        for (int i = 0; i < TM / 2; i++)
#pragma unroll
            for (int j = 0; j < TN; j++) {
                float2 u = unpack2f(acc[i][j]);
                g_logits[(size_t)(m0 + mb + 2 * i) * EE + nb + j] = u.x;
                g_logits[(size_t)(m0 + mb + 2 * i + 1) * EE + nb + j] = u.y;
            }
        return;
    }
    bx -= GATE_BLKS;
    if (bx < XS_B) { split_one(x, g_x_hi, g_x_lo, bx * 256 + tid); return; }
    bx -= XS_B;
    if (bx < E1_B) { split_one(e1_w, g_e1w_hi, g_e1w_lo, bx * 256 + tid); return; }
    bx -= E1_B;
    if (bx < S1_B) { split_one(sh1_w, g_s1w_hi, g_s1w_lo, bx * 256 + tid); return; }
    bx -= S1_B;
    if (bx < E2_B) { split_one(e2_w, g_e2w_hi, g_e2w_lo, bx * 256 + tid); return; }
    bx -= E2_B;
    if (bx < S2_B) { split_one(sh2_w, g_s2w_hi, g_s2w_lo, bx * 256 + tid); return; }
    bx -= S2_B;
    if (bx < ZO_B) {
        ((float4*)out)[bx * 256 + tid] = make_float4(0.f, 0.f, 0.f, 0.f);
        return;
    }
    bx -= ZO_B;
    int i = bx * 256 + tid;
    g_ident[i] = i;
    g_ones[i] = 1.0f;
    if (i < EE) { g_counts[i] = 0; g_prob_sum[i] = 0.0f; }
}

// ---------------- 2-CTA/SM GEMM, 3-stage ring, 1 barrier/iter ----------------
// BM=128, BN=128, BK=32; 128 threads (2x2 warp grid, 64x64 tiles); hi/lo packed rows.
// Stage = 32KB; 3 stages = 97KB/CTA; 2 CTAs/SM.
static constexpr int TG_BM = 128, TG_BN = 128, TG_BK = 32;
static constexpr int STG_B  = 16384;
static constexpr int STG_SZ = 32768;
static constexpr int TG_SMEM = 1024 + 3 * STG_SZ;   // 99328

template <int ACT, int SCALE, int CBF, int ATOMIC>
__global__ __launch_bounds__(128, 2) void mgemm(
    // expert side
    const __nv_bfloat16* __restrict__ Ah_e, const __nv_bfloat16* __restrict__ Al_e,
    const __nv_bfloat16* __restrict__ We_h, const __nv_bfloat16* __restrict__ We_l,
    const float* __restrict__ bias_e,
    const int* __restrict__ aidx_e,
    float* __restrict__ Cf_e, __nv_bfloat16* __restrict__ Ch_e, __nv_bfloat16* __restrict__ Cl_e,
    // shared side
    const __nv_bfloat16* __restrict__ Ah_s, const __nv_bfloat16* __restrict__ Al_s,
    const __nv_bfloat16* __restrict__ Ws_h, const __nv_bfloat16* __restrict__ Ws_l,
    const float* __restrict__ bias_s,
    float* __restrict__ Cf_s, __nv_bfloat16* __restrict__ Ch_s, __nv_bfloat16* __restrict__ Cl_s,
    int lda, int ldc, int N, int K) {
    const int z = blockIdx.z;
    const bool isSh = (z == EE);
    int M;
    const __nv_bfloat16 *Ah, *Al, *Wh, *Wl;
    const float *biasp, *rsp;
    const int *aidxp, *cidxp;
    float* Cf;
    __nv_bfloat16 *Ch, *Cl;
    if (isSh) {
        M = TOK;
        Ah = Ah_s; Al = Al_s; Wh = Ws_h; Wl = Ws_l; biasp = bias_s;
        aidxp = g_ident; cidxp = g_ident; rsp = g_ones;
        Cf = Cf_s; Ch = Ch_s; Cl = Cl_s;
    } else {
        int c = g_counts[z];
        M = c < CAP ? c : CAP;
        Ah = Ah_e; Al = Al_e;
        Wh = We_h + (size_t)z * N * K; Wl = We_l + (size_t)z * N * K;
        biasp = bias_e + (size_t)z * N;
        aidxp = aidx_e + z * CAP; cidxp = g_pairidx + z * CAP; rsp = g_score + z * CAP;
        Cf = Cf_e; Ch = Ch_e; Cl = Cl_e;
    }
    int m0 = blockIdx.x * TG_BM;
    if (m0 >= M) return;
    int n0 = blockIdx.y * TG_BN;

    extern __shared__ char smem_raw[];
    uint32_t sb = smem_u32(smem_raw);
    uint32_t tiles = (sb + 1023u) & ~1023u;

    const int tid = threadIdx.x;
    const int lane = tid & 31;
    const int w = tid >> 5;
    const int wm = w & 1, wn = w >> 1;          // 2x2 warp grid, 64x64 tiles

    // ---- cp.async fill geometry ----
    const int c8 = tid & 7;
    const int r0 = tid >> 3;                    // 0..15
    const bool isHi = c8 < 4;
    const int kcol = (c8 & 3) * 8;
    const uint32_t offBase = (uint32_t)(r0 * 128 + ((c8 ^ (r0 & 7)) << 4));
    const char* aSrc[8];
    uint32_t aSz[8];
#pragma unroll
    for (int i = 0; i < 8; i++) {
        int gm = m0 + r0 + 16 * i;
        bool v = gm < M;
        int ar = v ? aidxp[gm] : 0;
        const __nv_bfloat16* base = isHi ? Ah : Al;
        aSrc[i] = (const char*)(base + (size_t)ar * lda + kcol);
        aSz[i] = v ? 16u : 0u;
    }
    const char* bSrc = (const char*)((isHi ? Wh : Wl) + (size_t)(n0 + r0) * K + kcol);

#define FILL(kk, buf)                                                             \
    {                                                                             \
        uint32_t sg = tiles + (uint32_t)(buf) * STG_SZ;                           \
        _Pragma("unroll")                                                         \
        for (int i = 0; i < 8; i++)                                               \
            cpa16(sg + offBase + i * 2048, aSrc[i] + (size_t)(kk) * 2, aSz[i]);   \
        _Pragma("unroll")                                                         \
        for (int i = 0; i < 8; i++)                                               \
            cpa16(sg + STG_B + offBase + i * 2048,                                \
                  bSrc + (size_t)(kk) * 2 + (size_t)i * 16 * K * 2, 16);          \
    }

    // ---- ldmatrix per-lane geometry ----
    const int arow16 = (lane & 7) | (lane & 8);
    const uint32_t ak = (lane & 16) ? 1u : 0u;
    const int brow16 = (lane & 7) | ((lane & 16) >> 1);
    const uint32_t bk = (lane & 8) ? 1u : 0u;
    uint32_t artA[4], artB[4];
#pragma unroll
    for (int mi = 0; mi < 4; mi++) {
        int row = wm * 64 + mi * 16 + arow16;
        artA[mi] = (uint32_t)(row * 128) | ((uint32_t)(row & 7) << 4);
    }
#pragma unroll
    for (int nj = 0; nj < 4; nj++) {
        int row = wn * 64 + nj * 16 + brow16;
        artB[nj] = (uint32_t)(row * 128) | ((uint32_t)(row & 7) << 4);
    }

    float acc[4][8][4];
#pragma unroll
    for (int i = 0; i < 4; i++)
#pragma unroll
        for (int j = 0; j < 8; j++)
#pragma unroll
            for (int q = 0; q < 4; q++) acc[i][j][q] = 0.0f;

    const int KT = K / TG_BK;

    FILL(0, 0);
    CP_COMMIT();
    FILL(TG_BK, 1);
    CP_COMMIT();

    int cur = 0, nxt = 2;                       // buffer of t, buffer of t+2
    for (int t = 0; t < KT; t++) {
        CP_WAIT1();
        __syncthreads();
        // prefetch t+2 into ring slot (last read in iteration t-1; safe after the barrier)
        if (t + 2 < KT) FILL((t + 2) * TG_BK, nxt);
        CP_COMMIT();
        const uint32_t sgA = tiles + (uint32_t)cur * STG_SZ;
        const uint32_t sgB = sgA + STG_B;
#pragma unroll
        for (int ks = 0; ks < 2; ks++) {
            const uint32_t cA = (uint32_t)(ks * 2) + ak;
            uint32_t ahf[4][4], alf[4][4];
#pragma unroll
            for (int mi = 0; mi < 4; mi++) {
                LDSM4(ahf[mi], sgA + (artA[mi] ^ (cA << 4)));
                LDSM4(alf[mi], sgA + (artA[mi] ^ ((cA + 4) << 4)));
            }
            const uint32_t cB = (uint32_t)(ks * 2) + bk;
#pragma unroll
            for (int nj = 0; nj < 4; nj++) {
                uint32_t bh[4], bl[4];
                LDSM4(bh, sgB + (artB[nj] ^ (cB << 4)));
                LDSM4(bl, sgB + (artB[nj] ^ ((cB + 4) << 4)));
#pragma unroll
                for (int mi = 0; mi < 4; mi++) {
                    hmma(acc[mi][2 * nj],     ahf[mi], bh[0], bh[1]);
                    hmma(acc[mi][2 * nj + 1], ahf[mi], bh[2], bh[3]);
                }
#pragma unroll
                for (int mi = 0; mi < 4; mi++) {
                    hmma(acc[mi][2 * nj],     ahf[mi], bl[0], bl[1]);
                    hmma(acc[mi][2 * nj + 1], ahf[mi], bl[2], bl[3]);
                }
#pragma unroll
                for (int mi = 0; mi < 4; mi++) {
                    hmma(acc[mi][2 * nj],     alf[mi], bh[0], bh[1]);
                    hmma(acc[mi][2 * nj + 1], alf[mi], bh[2], bh[3]);
                }
            }
        }
        cur = cur + 1 == 3 ? 0 : cur + 1;
        nxt = nxt + 1 == 3 ? 0 : nxt + 1;
    }
#undef FILL

    // ---- epilogue ----
    const int g = lane >> 2, q2 = (lane & 3) * 2;
#pragma unroll
    for (int mi = 0; mi < 4; mi++) {
        int ml = m0 + wm * 64 + mi * 16 + g;
        int mh = ml + 8;
        bool vlo = ml < M, vhi = mh < M;
        int cr0 = 0, cr1 = 0;
        float s0 = 1.0f, s1 = 1.0f;
        if (vlo) { cr0 = cidxp[ml]; if (SCALE) s0 = rsp[ml]; }
        if (vhi) { cr1 = cidxp[mh]; if (SCALE) s1 = rsp[mh]; }
        if (ATOMIC) {
            if (vlo && !isSh) cr0 = cr0 / TOPK;
            if (vhi && !isSh) cr1 = cr1 / TOPK;
        }
#pragma unroll
        for (int nf = 0; nf < 8; nf++) {
            int gn = n0 + wn * 64 + nf * 8 + q2;
            float b0 = biasp[gn], b1 = biasp[gn + 1];
            float v0 = acc[mi][nf][0] + b0, v1 = acc[mi][nf][1] + b1;
            float v2 = acc[mi][nf][2] + b0, v3 = acc[mi][nf][3] + b1;
            if (ACT) { v0 = gelu_ex(v0); v1 = gelu_ex(v1); v2 = gelu_ex(v2); v3 = gelu_ex(v3); }
            if (SCALE) { v0 *= s0; v1 *= s0; v2 *= s1; v3 *= s1; }
            if (!CBF) {
                if (ATOMIC) {
                    if (vlo) {
                        float* p = Cf + (size_t)cr0 * ldc + gn;
                        atomicAdd(p, v0); atomicAdd(p + 1, v1);
                    }
                    if (vhi) {
                        float* p = Cf + (size_t)cr1 * ldc + gn;
                        atomicAdd(p, v2); atomicAdd(p + 1, v3);
                    }
                } else {
                    if (vlo) *(float2*)(Cf + (size_t)cr0 * ldc + gn) = make_float2(v0, v1);
                    if (vhi) *(float2*)(Cf + (size_t)cr1 * ldc + gn) = make_float2(v2, v3);
                }
            } else {
                if (vlo) {
                    uint32_t h, l;
                    split2(v0, v1, h, l);
                    *(uint32_t*)(Ch + (size_t)cr0 * ldc + gn) = h;
                    *(uint32_t*)(Cl + (size_t)cr0 * ldc + gn) = l;
                }
                if (vhi) {
                    uint32_t h, l;
                    split2(v2, v3, h, l);
                    *(uint32_t*)(Ch + (size_t)cr1 * ldc + gn) = h;
                    *(uint32_t*)(Cl + (size_t)cr1 * ldc + gn) = l;
                }
            }
        }
    }
}

// ---------------- softmax + top-k + routing + prob accumulation ----------------
__global__ void topk_route_kernel() {
    int gw = (blockIdx.x * blockDim.x + threadIdx.x) >> 5;
    int lane = threadIdx.x & 31;
    if (gw >= TOK) return;
    float2 v = ((const float2*)(g_logits + (size_t)gw * EE))[lane];
    float m = fmaxf(v.x, v.y);
#pragma unroll
    for (int o = 16; o > 0; o >>= 1) m = fmaxf(m, __shfl_xor_sync(FULLMASK, m, o));
    float e0 = __expf(v.x - m), e1 = __expf(v.y - m);
    float s = e0 + e1;
#pragma unroll
    for (int o = 16; o > 0; o >>= 1) s += __shfl_xor_sync(FULLMASK, s, o);
    float inv = 1.0f / s;
    float p0 = e0 * inv, p1 = e1 * inv;
    atomicAdd(&g_prob_sum[2 * lane], p0);
    atomicAdd(&g_prob_sum[2 * lane + 1], p1);

    float a0 = p0, a1 = p1;
    for (int k = 0; k < TOPK; k++) {
        float bvv; int bi;
        if (a0 >= a1) { bvv = a0; bi = 2 * lane; }
        else          { bvv = a1; bi = 2 * lane + 1; }
#pragma unroll
        for (int o = 16; o > 0; o >>= 1) {
            float ov = __shfl_xor_sync(FULLMASK, bvv, o);
            int oi = __shfl_xor_sync(FULLMASK, bi, o);
            if (ov > bvv || (ov == bvv && oi < bi)) { bvv = ov; bi = oi; }
        }
        if ((bi >> 1) == lane) {
            if (bi & 1) a1 = -1.0f; else a0 = -1.0f;
            int slot = atomicAdd(&g_counts[bi], 1);
            if (slot < CAP) {
                int base = bi * CAP + slot;
                g_tok[base] = gw;
                g_pairidx[base] = gw * TOPK + k;
                g_score[base] = bvv;
            }
        }
    }
}

// ---------------- scalar outputs ----------------
__global__ void finalize_kernel(float* __restrict__ out) {
    __shared__ float sh[EE];
    int e = threadIdx.x;
    float freq = (float)g_counts[e] / (float)(TOK * TOPK);
    float prob = g_prob_sum[e] * (1.0f / (float)TOK);
    out[OUT_MAIN + 1 + e] = freq;
    out[OUT_MAIN + 1 + EE + e] = prob;
    sh[e] = freq * prob;
    __syncthreads();
    if (e == 0) {
        float s = 0.0f;
        for (int i = 0; i < EE; i++) s += sh[i];
        out[OUT_MAIN] = 0.01f * s;
    }
}

// ---------------- launch ----------------
extern "C" void kernel_launch(void* const* d_in, const int* in_sizes, int n_in,
                              void* d_out, int out_size) {
    const float* x      = (const float*)d_in[0];
    const float* gate_w = (const float*)d_in[1];
    const float* sh1_w  = (const float*)d_in[2];
    const float* sh1_b  = (const float*)d_in[3];
    const float* sh2_w  = (const float*)d_in[4];
    const float* sh2_b  = (const float*)d_in[5];
    const float* e1_w   = (const float*)d_in[6];
    const float* e1_b   = (const float*)d_in[7];
    const float* e2_w   = (const float*)d_in[8];
    const float* e2_b   = (const float*)d_in[9];
    float* out = (float*)d_out;

    int *p_tok, *p_pair;
    __nv_bfloat16 *p_x_hi, *p_x_lo, *p_s1h, *p_s1l, *p_s2h, *p_s2l;
    __nv_bfloat16 *p_e1h, *p_e1l, *p_e2h, *p_e2l;
    __nv_bfloat16 *p_shh_hi, *p_shh_lo, *p_h_hi, *p_h_lo;
    cudaGetSymbolAddress((void**)&p_tok, g_tok);
    cudaGetSymbolAddress((void**)&p_pair, g_pairidx);
    cudaGetSymbolAddress((void**)&p_x_hi, g_x_hi);
    cudaGetSymbolAddress((void**)&p_x_lo, g_x_lo);
    cudaGetSymbolAddress((void**)&p_s1h, g_s1w_hi);
    cudaGetSymbolAddress((void**)&p_s1l, g_s1w_lo);
    cudaGetSymbolAddress((void**)&p_s2h, g_s2w_hi);
    cudaGetSymbolAddress((void**)&p_s2l, g_s2w_lo);
    cudaGetSymbolAddress((void**)&p_e1h, g_e1w_hi);
    cudaGetSymbolAddress((void**)&p_e1l, g_e1w_lo);
    cudaGetSymbolAddress((void**)&p_e2h, g_e2w_hi);
    cudaGetSymbolAddress((void**)&p_e2l, g_e2w_lo);
    cudaGetSymbolAddress((void**)&p_shh_hi, g_shh_hi);
    cudaGetSymbolAddress((void**)&p_shh_lo, g_shh_lo);
    cudaGetSymbolAddress((void**)&p_h_hi, g_h_hi);
    cudaGetSymbolAddress((void**)&p_h_lo, g_h_lo);

    cudaFuncSetAttribute(mgemm<1, 0, 1, 0>,
                         cudaFuncAttributeMaxDynamicSharedMemorySize, TG_SMEM);
    cudaFuncSetAttribute(mgemm<0, 1, 0, 1>,
                         cudaFuncAttributeMaxDynamicSharedMemorySize, TG_SMEM);

    // fused prep (R11-exact)
    prep_kernel<<<PREP_BLKS, 256>>>(x, gate_w, e1_w, sh1_w, e2_w, sh2_w, out);

    topk_route_kernel<<<TOK / 8, 256>>>();
    finalize_kernel<<<1, 64>>>(out);

    // GEMM1: experts (gather tok -> h) + shared (x -> shh)
    mgemm<1, 0, 1, 0><<<dim3(TOK / 128, HH / 128, EE + 1), 128, TG_SMEM>>>(
        p_x_hi, p_x_lo, p_e1h, p_e1l, e1_b, p_tok,
        nullptr, p_h_hi, p_h_lo,
        p_x_hi, p_x_lo, p_s1h, p_s1l, sh1_b,
        nullptr, p_shh_hi, p_shh_lo,
        DD, HH, HH, DD);

    // GEMM2: experts + shared; fused combine via atomicAdd into out
    mgemm<0, 1, 0, 1><<<dim3(TOK / 128, DD / 128, EE + 1), 128, TG_SMEM>>>(
        p_h_hi, p_h_lo, p_e2h, p_e2l, e2_b, p_pair,
        out, nullptr, nullptr,
        p_shh_hi, p_shh_lo, p_s2h, p_s2l, sh2_b,
        out, nullptr, nullptr,
        HH, DD, DD, HH);
}

// round 17
// speedup vs baseline: 1.0574x; 1.0164x over previous
#include <cuda_runtime.h>
#include <cuda_bf16.h>
#include <math.h>
#include <stdint.h>

// ---------------- problem constants ----------------
static constexpr int TOK   = 4096;
static constexpr int DD    = 768;
static constexpr int HH    = 1536;
static constexpr int EE    = 64;
static constexpr int TOPK  = 6;
static constexpr int CAP   = 1536;
static constexpr int NPAIR = TOK * TOPK;
static constexpr int OUT_MAIN = TOK * DD;

#define FULLMASK 0xFFFFFFFFu

// ---------------- scratch ----------------
__device__ float g_logits[TOK * EE];
__device__ float g_prob_sum[EE];
__device__ int   g_counts[EE];
__device__ int   g_tok[EE * CAP];
__device__ int   g_pairidx[EE * CAP];
__device__ float g_score[EE * CAP];
__device__ int   g_ident[TOK];
__device__ float g_ones[TOK];
__device__ __nv_bfloat16 g_x_hi[(size_t)TOK * DD];
__device__ __nv_bfloat16 g_x_lo[(size_t)TOK * DD];
__device__ __nv_bfloat16 g_s1w_hi[(size_t)HH * DD];
__device__ __nv_bfloat16 g_s1w_lo[(size_t)HH * DD];
__device__ __nv_bfloat16 g_s2w_hi[(size_t)DD * HH];
__device__ __nv_bfloat16 g_s2w_lo[(size_t)DD * HH];
__device__ __nv_bfloat16 g_e1w_hi[(size_t)EE * HH * DD];
__device__ __nv_bfloat16 g_e1w_lo[(size_t)EE * HH * DD];
__device__ __nv_bfloat16 g_e2w_hi[(size_t)EE * DD * HH];
__device__ __nv_bfloat16 g_e2w_lo[(size_t)EE * DD * HH];
__device__ __nv_bfloat16 g_shh_hi[(size_t)TOK * HH];
__device__ __nv_bfloat16 g_shh_lo[(size_t)TOK * HH];
__device__ __nv_bfloat16 g_h_hi[(size_t)NPAIR * HH];
__device__ __nv_bfloat16 g_h_lo[(size_t)NPAIR * HH];

static constexpr int XS_N8 = TOK * DD / 8;
static constexpr int S1_N8 = HH * DD / 8;
static constexpr int S2_N8 = DD * HH / 8;
static constexpr int E1_N8 = EE * HH * DD / 8;
static constexpr int E2_N8 = EE * DD * HH / 8;

// ---------------- helpers ----------------
__device__ __forceinline__ uint32_t smem_u32(const void* p) {
    uint32_t a;
    asm("{ .reg .u64 t; cvta.to.shared.u64 t, %1; cvt.u32.u64 %0, t; }" : "=r"(a) : "l"(p));
    return a;
}
__device__ __forceinline__ uint32_t cvt_bf2(float hi_upper, float lo_lower) {
    uint32_t r;
    asm("cvt.rn.bf16x2.f32 %0, %1, %2;" : "=r"(r) : "f"(hi_upper), "f"(lo_lower));
    return r;
}
__device__ __forceinline__ void split2(float v0, float v1, uint32_t& h, uint32_t& l) {
    h = cvt_bf2(v1, v0);
    float f0 = __uint_as_float(h << 16);
    float f1 = __uint_as_float(h & 0xffff0000u);
    l = cvt_bf2(v1 - f1, v0 - f0);
}
__device__ __forceinline__ void split_one(const float* __restrict__ src,
                                          __nv_bfloat16* __restrict__ hi,
                                          __nv_bfloat16* __restrict__ lo, int i) {
    const float4* s = (const float4*)src + (size_t)i * 2;
    float4 v0 = s[0], v1 = s[1];
    uint32_t h0, l0, h1, l1, h2, l2, h3, l3;
    split2(v0.x, v0.y, h0, l0);
    split2(v0.z, v0.w, h1, l1);
    split2(v1.x, v1.y, h2, l2);
    split2(v1.z, v1.w, h3, l3);
    ((uint4*)hi)[i] = make_uint4(h0, h1, h2, h3);
    ((uint4*)lo)[i] = make_uint4(l0, l1, l2, l3);
}
__device__ __forceinline__ float gelu_ex(float x) {
    return 0.5f * x * (1.0f + erff(x * 0.70710678118654752f));
}
__device__ __forceinline__ void atomicAdd2(float* p, float a, float b) {
    asm volatile("red.global.add.v2.f32 [%0], {%1, %2};" :: "l"(p), "f"(a), "f"(b) : "memory");
}
__device__ __forceinline__ void hmma(float* c, const uint32_t* a, uint32_t b0, uint32_t b1) {
    asm volatile(
        "mma.sync.aligned.m16n8k16.row.col.f32.bf16.bf16.f32 "
        "{%0,%1,%2,%3}, {%4,%5,%6,%7}, {%8,%9}, {%0,%1,%2,%3};"
        : "+f"(c[0]), "+f"(c[1]), "+f"(c[2]), "+f"(c[3])
        : "r"(a[0]), "r"(a[1]), "r"(a[2]), "r"(a[3]), "r"(b0), "r"(b1));
}
#define LDSM4(r, a) \
    asm volatile("ldmatrix.sync.aligned.m8n8.x4.shared.b16 {%0,%1,%2,%3}, [%4];" \
                 : "=r"((r)[0]), "=r"((r)[1]), "=r"((r)[2]), "=r"((r)[3]) : "r"(a))
__device__ __forceinline__ void cpa16(uint32_t dst, const void* src, uint32_t srcsz) {
    asm volatile("cp.async.cg.shared.global [%0], [%1], 16, %2;"
                 :: "r"(dst), "l"(src), "r"(srcsz));
}
#define CP_COMMIT() asm volatile("cp.async.commit_group;" ::: "memory")
#define CP_WAIT1()  asm volatile("cp.async.wait_group 1;" ::: "memory")

__device__ __forceinline__ unsigned long long ffma2(unsigned long long a,
                                                    unsigned long long b,
                                                    unsigned long long c) {
    unsigned long long d;
    asm("fma.rn.f32x2 %0, %1, %2, %3;" : "=l"(d) : "l"(a), "l"(b), "l"(c));
    return d;
}
__device__ __forceinline__ unsigned long long pack2f(float x) {
    unsigned long long d;
    asm("mov.b64 %0, {%1, %1};" : "=l"(d) : "f"(x));
    return d;
}
__device__ __forceinline__ float2 unpack2f(unsigned long long v) {
    float2 r;
    asm("mov.b64 {%0, %1}, %2;" : "=f"(r.x), "=f"(r.y) : "l"(v));
    return r;
}

// ---------------- fused prep (R11-exact) ----------------
static constexpr int GATE_BLKS = 64;
static constexpr int XS_B = XS_N8 / 256;
static constexpr int E1_B = E1_N8 / 256;
static constexpr int S1_B = S1_N8 / 256;
static constexpr int E2_B = E2_N8 / 256;
static constexpr int S2_B = S2_N8 / 256;
static constexpr int ZO_B = TOK * DD / 4 / 256;
static constexpr int RS_B = TOK / 256;
static constexpr int PREP_BLKS =
    GATE_BLKS + XS_B + E1_B + S1_B + E2_B + S2_B + ZO_B + RS_B;

__global__ __launch_bounds__(256) void prep_kernel(
    const float* __restrict__ x, const float* __restrict__ gate_w,
    const float* __restrict__ e1_w, const float* __restrict__ sh1_w,
    const float* __restrict__ e2_w, const float* __restrict__ sh2_w,
    float* __restrict__ out) {
    int bx = blockIdx.x;
    int tid = threadIdx.x;
    if (bx < GATE_BLKS) {
        constexpr int BM = 64, BN = 64, BK = 16, TM = 4, TN = 4;
        __shared__ __align__(16) float As[BK][BM + 4];
        __shared__ __align__(16) float Bs[BK][BN + 4];
        int m0 = bx * BM;
        int tx = tid % (BN / TN), ty = tid / (BN / TN);
        int mb = ty * TM, nb = tx * TN;
        unsigned long long acc[TM / 2][TN];
#pragma unroll
        for (int i = 0; i < TM / 2; i++)
#pragma unroll
            for (int j = 0; j < TN; j++) acc[i][j] = 0ull;
        for (int kk = 0; kk < DD; kk += BK) {
#pragma unroll
            for (int it = 0; it < BM * BK / 4; it += 256) {
                int i = it + tid;
                int m = i / (BK / 4), k4 = (i % (BK / 4)) * 4;
                float4 v = *(const float4*)(x + (size_t)(m0 + m) * DD + kk + k4);
                As[k4 + 0][m] = v.x; As[k4 + 1][m] = v.y;
                As[k4 + 2][m] = v.z; As[k4 + 3][m] = v.w;
            }
#pragma unroll
            for (int it = 0; it < BN * BK / 4; it += 256) {
                int i = it + tid;
                int n = i / (BK / 4), k4 = (i % (BK / 4)) * 4;
                float4 v = *(const float4*)(gate_w + (size_t)n * DD + kk + k4);
                Bs[k4 + 0][n] = v.x; Bs[k4 + 1][n] = v.y;
                Bs[k4 + 2][n] = v.z; Bs[k4 + 3][n] = v.w;
            }
            __syncthreads();
#pragma unroll
            for (int k = 0; k < BK; k++) {
                unsigned long long a2[TM / 2];
                ulonglong2 av = *(const ulonglong2*)&As[k][mb];
                a2[0] = av.x; a2[1] = av.y;
                float4 b4 = *(const float4*)&Bs[k][nb];
                float bv[4] = {b4.x, b4.y, b4.z, b4.w};
#pragma unroll
                for (int j = 0; j < TN; j++) {
                    unsigned long long b2 = pack2f(bv[j]);
#pragma unroll
                    for (int i = 0; i < TM / 2; i++) acc[i][j] = ffma2(a2[i], b2, acc[i][j]);
                }
            }
            __syncthreads();
        }
#pragma unroll
        for (int i = 0; i < TM / 2; i++)
#pragma unroll
            for (int j = 0; j < TN; j++) {
                float2 u = unpack2f(acc[i][j]);
                g_logits[(size_t)(m0 + mb + 2 * i) * EE + nb + j] = u.x;
                g_logits[(size_t)(m0 + mb + 2 * i + 1) * EE + nb + j] = u.y;
            }
        return;
    }
    bx -= GATE_BLKS;
    if (bx < XS_B) { split_one(x, g_x_hi, g_x_lo, bx * 256 + tid); return; }
    bx -= XS_B;
    if (bx < E1_B) { split_one(e1_w, g_e1w_hi, g_e1w_lo, bx * 256 + tid); return; }
    bx -= E1_B;
    if (bx < S1_B) { split_one(sh1_w, g_s1w_hi, g_s1w_lo, bx * 256 + tid); return; }
    bx -= S1_B;
    if (bx < E2_B) { split_one(e2_w, g_e2w_hi, g_e2w_lo, bx * 256 + tid); return; }
    bx -= E2_B;
    if (bx < S2_B) { split_one(sh2_w, g_s2w_hi, g_s2w_lo, bx * 256 + tid); return; }
    bx -= S2_B;
    if (bx < ZO_B) {
        ((float4*)out)[bx * 256 + tid] = make_float4(0.f, 0.f, 0.f, 0.f);
        return;
    }
    bx -= ZO_B;
    int i = bx * 256 + tid;
    g_ident[i] = i;
    g_ones[i] = 1.0f;
    if (i < EE) { g_counts[i] = 0; g_prob_sum[i] = 0.0f; }
}

// ---------------- 2-CTA/SM GEMM, 3-stage ring, 1 barrier/iter (R16) ----------------
static constexpr int TG_BM = 128, TG_BN = 128, TG_BK = 32;
static constexpr int STG_B  = 16384;
static constexpr int STG_SZ = 32768;
static constexpr int TG_SMEM = 1024 + 3 * STG_SZ;   // 99328

template <int ACT, int SCALE, int CBF, int ATOMIC>
__global__ __launch_bounds__(128, 2) void mgemm(
    // expert side
    const __nv_bfloat16* __restrict__ Ah_e, const __nv_bfloat16* __restrict__ Al_e,
    const __nv_bfloat16* __restrict__ We_h, const __nv_bfloat16* __restrict__ We_l,
    const float* __restrict__ bias_e,
    const int* __restrict__ aidx_e,
    float* __restrict__ Cf_e, __nv_bfloat16* __restrict__ Ch_e, __nv_bfloat16* __restrict__ Cl_e,
    // shared side
    const __nv_bfloat16* __restrict__ Ah_s, const __nv_bfloat16* __restrict__ Al_s,
    const __nv_bfloat16* __restrict__ Ws_h, const __nv_bfloat16* __restrict__ Ws_l,
    const float* __restrict__ bias_s,
    float* __restrict__ Cf_s, __nv_bfloat16* __restrict__ Ch_s, __nv_bfloat16* __restrict__ Cl_s,
    int lda, int ldc, int N, int K) {
    const int z = blockIdx.z;
    const bool isSh = (z == EE);
    int M;
    const __nv_bfloat16 *Ah, *Al, *Wh, *Wl;
    const float *biasp, *rsp;
    const int *aidxp, *cidxp;
    float* Cf;
    __nv_bfloat16 *Ch, *Cl;
    if (isSh) {
        M = TOK;
        Ah = Ah_s; Al = Al_s; Wh = Ws_h; Wl = Ws_l; biasp = bias_s;
        aidxp = g_ident; cidxp = g_ident; rsp = g_ones;
        Cf = Cf_s; Ch = Ch_s; Cl = Cl_s;
    } else {
        int c = g_counts[z];
        M = c < CAP ? c : CAP;
        Ah = Ah_e; Al = Al_e;
        Wh = We_h + (size_t)z * N * K; Wl = We_l + (size_t)z * N * K;
        biasp = bias_e + (size_t)z * N;
        aidxp = aidx_e + z * CAP; cidxp = g_pairidx + z * CAP; rsp = g_score + z * CAP;
        Cf = Cf_e; Ch = Ch_e; Cl = Cl_e;
    }
    int m0 = blockIdx.x * TG_BM;
    if (m0 >= M) return;
    int n0 = blockIdx.y * TG_BN;

    extern __shared__ char smem_raw[];
    uint32_t sb = smem_u32(smem_raw);
    uint32_t tiles = (sb + 1023u) & ~1023u;

    const int tid = threadIdx.x;
    const int lane = tid & 31;
    const int w = tid >> 5;
    const int wm = w & 1, wn = w >> 1;

    // ---- cp.async fill geometry ----
    const int c8 = tid & 7;
    const int r0 = tid >> 3;
    const bool isHi = c8 < 4;
    const int kcol = (c8 & 3) * 8;
    const uint32_t offBase = (uint32_t)(r0 * 128 + ((c8 ^ (r0 & 7)) << 4));
    const char* aSrc[8];
    uint32_t aSz[8];
#pragma unroll
    for (int i = 0; i < 8; i++) {
        int gm = m0 + r0 + 16 * i;
        bool v = gm < M;
        int ar = v ? aidxp[gm] : 0;
        const __nv_bfloat16* base = isHi ? Ah : Al;
        aSrc[i] = (const char*)(base + (size_t)ar * lda + kcol);
        aSz[i] = v ? 16u : 0u;
    }
    const char* bSrc = (const char*)((isHi ? Wh : Wl) + (size_t)(n0 + r0) * K + kcol);

#define FILL(kk, buf)                                                             \
    {                                                                             \
        uint32_t sg = tiles + (uint32_t)(buf) * STG_SZ;                           \
        _Pragma("unroll")                                                         \
        for (int i = 0; i < 8; i++)                                               \
            cpa16(sg + offBase + i * 2048, aSrc[i] + (size_t)(kk) * 2, aSz[i]);   \
        _Pragma("unroll")                                                         \
        for (int i = 0; i < 8; i++)                                               \
            cpa16(sg + STG_B + offBase + i * 2048,                                \
                  bSrc + (size_t)(kk) * 2 + (size_t)i * 16 * K * 2, 16);          \
    }

    // ---- ldmatrix per-lane geometry ----
    const int arow16 = (lane & 7) | (lane & 8);
    const uint32_t ak = (lane & 16) ? 1u : 0u;
    const int brow16 = (lane & 7) | ((lane & 16) >> 1);
    const uint32_t bk = (lane & 8) ? 1u : 0u;
    uint32_t artA[4], artB[4];
#pragma unroll
    for (int mi = 0; mi < 4; mi++) {
        int row = wm * 64 + mi * 16 + arow16;
        artA[mi] = (uint32_t)(row * 128) | ((uint32_t)(row & 7) << 4);
    }
#pragma unroll
    for (int nj = 0; nj < 4; nj++) {
        int row = wn * 64 + nj * 16 + brow16;
        artB[nj] = (uint32_t)(row * 128) | ((uint32_t)(row & 7) << 4);
    }

    float acc[4][8][4];
#pragma unroll
    for (int i = 0; i < 4; i++)
#pragma unroll
        for (int j = 0; j < 8; j++)
#pragma unroll
            for (int q = 0; q < 4; q++) acc[i][j][q] = 0.0f;

    const int KT = K / TG_BK;

    FILL(0, 0);
    CP_COMMIT();
    FILL(TG_BK, 1);
    CP_COMMIT();

    int cur = 0, nxt = 2;
    for (int t = 0; t < KT; t++) {
        CP_WAIT1();
        __syncthreads();
        if (t + 2 < KT) FILL((t + 2) * TG_BK, nxt);
        CP_COMMIT();
        const uint32_t sgA = tiles + (uint32_t)cur * STG_SZ;
        const uint32_t sgB = sgA + STG_B;
#pragma unroll
        for (int ks = 0; ks < 2; ks++) {
            const uint32_t cA = (uint32_t)(ks * 2) + ak;
            uint32_t ahf[4][4], alf[4][4];
#pragma unroll
            for (int mi = 0; mi < 4; mi++) {
                LDSM4(ahf[mi], sgA + (artA[mi] ^ (cA << 4)));
                LDSM4(alf[mi], sgA + (artA[mi] ^ ((cA + 4) << 4)));
            }
            const uint32_t cB = (uint32_t)(ks * 2) + bk;
#pragma unroll
            for (int nj = 0; nj < 4; nj++) {
                uint32_t bh[4], bl[4];
                LDSM4(bh, sgB + (artB[nj] ^ (cB << 4)));
                LDSM4(bl, sgB + (artB[nj] ^ ((cB + 4) << 4)));
#pragma unroll
                for (int mi = 0; mi < 4; mi++) {
                    hmma(acc[mi][2 * nj],     ahf[mi], bh[0], bh[1]);
                    hmma(acc[mi][2 * nj + 1], ahf[mi], bh[2], bh[3]);
                }
#pragma unroll
                for (int mi = 0; mi < 4; mi++) {
                    hmma(acc[mi][2 * nj],     ahf[mi], bl[0], bl[1]);
                    hmma(acc[mi][2 * nj + 1], ahf[mi], bl[2], bl[3]);
                }
#pragma unroll
                for (int mi = 0; mi < 4; mi++) {
                    hmma(acc[mi][2 * nj],     alf[mi], bh[0], bh[1]);
                    hmma(acc[mi][2 * nj + 1], alf[mi], bh[2], bh[3]);
                }
            }
        }
        cur = cur + 1 == 3 ? 0 : cur + 1;
        nxt = nxt + 1 == 3 ? 0 : nxt + 1;
    }
#undef FILL

    // ---- epilogue ----
    const int g = lane >> 2, q2 = (lane & 3) * 2;
#pragma unroll
    for (int mi = 0; mi < 4; mi++) {
        int ml = m0 + wm * 64 + mi * 16 + g;
        int mh = ml + 8;
        bool vlo = ml < M, vhi = mh < M;
        int cr0 = 0, cr1 = 0;
        float s0 = 1.0f, s1 = 1.0f;
        if (vlo) { cr0 = cidxp[ml]; if (SCALE) s0 = rsp[ml]; }
        if (vhi) { cr1 = cidxp[mh]; if (SCALE) s1 = rsp[mh]; }
        if (ATOMIC) {
            if (vlo && !isSh) cr0 = cr0 / TOPK;
            if (vhi && !isSh) cr1 = cr1 / TOPK;
        }
#pragma unroll
        for (int nf = 0; nf < 8; nf++) {
            int gn = n0 + wn * 64 + nf * 8 + q2;
            float b0 = biasp[gn], b1 = biasp[gn + 1];
            float v0 = acc[mi][nf][0] + b0, v1 = acc[mi][nf][1] + b1;
            float v2 = acc[mi][nf][2] + b0, v3 = acc[mi][nf][3] + b1;
            if (ACT) { v0 = gelu_ex(v0); v1 = gelu_ex(v1); v2 = gelu_ex(v2); v3 = gelu_ex(v3); }
            if (SCALE) { v0 *= s0; v1 *= s0; v2 *= s1; v3 *= s1; }
            if (!CBF) {
                if (ATOMIC) {
                    if (vlo) atomicAdd2(Cf + (size_t)cr0 * ldc + gn, v0, v1);
                    if (vhi) atomicAdd2(Cf + (size_t)cr1 * ldc + gn, v2, v3);
                } else {
                    if (vlo) *(float2*)(Cf + (size_t)cr0 * ldc + gn) = make_float2(v0, v1);
                    if (vhi) *(float2*)(Cf + (size_t)cr1 * ldc + gn) = make_float2(v2, v3);
                }
            } else {
                if (vlo) {
                    uint32_t h, l;
                    split2(v0, v1, h, l);
                    *(uint32_t*)(Ch + (size_t)cr0 * ldc + gn) = h;
                    *(uint32_t*)(Cl + (size_t)cr0 * ldc + gn) = l;
                }
                if (vhi) {
                    uint32_t h, l;
                    split2(v2, v3, h, l);
                    *(uint32_t*)(Ch + (size_t)cr1 * ldc + gn) = h;
                    *(uint32_t*)(Cl + (size_t)cr1 * ldc + gn) = l;
                }
            }
        }
    }
}

// ---------------- softmax + top-k + routing + prob accumulation ----------------
__global__ void topk_route_kernel() {
    int gw = (blockIdx.x * blockDim.x + threadIdx.x) >> 5;
    int lane = threadIdx.x & 31;
    if (gw >= TOK) return;
    float2 v = ((const float2*)(g_logits + (size_t)gw * EE))[lane];
    float m = fmaxf(v.x, v.y);
#pragma unroll
    for (int o = 16; o > 0; o >>= 1) m = fmaxf(m, __shfl_xor_sync(FULLMASK, m, o));
    float e0 = __expf(v.x - m), e1 = __expf(v.y - m);
    float s = e0 + e1;
#pragma unroll
    for (int o = 16; o > 0; o >>= 1) s += __shfl_xor_sync(FULLMASK, s, o);
    float inv = 1.0f / s;
    float p0 = e0 * inv, p1 = e1 * inv;
    atomicAdd2(&g_prob_sum[2 * lane], p0, p1);

    float a0 = p0, a1 = p1;
    for (int k = 0; k < TOPK; k++) {
        float bvv; int bi;
        if (a0 >= a1) { bvv = a0; bi = 2 * lane; }
        else          { bvv = a1; bi = 2 * lane + 1; }
#pragma unroll
        for (int o = 16; o > 0; o >>= 1) {
            float ov = __shfl_xor_sync(FULLMASK, bvv, o);
            int oi = __shfl_xor_sync(FULLMASK, bi, o);
            if (ov > bvv || (ov == bvv && oi < bi)) { bvv = ov; bi = oi; }
        }
        if ((bi >> 1) == lane) {
            if (bi & 1) a1 = -1.0f; else a0 = -1.0f;
            int slot = atomicAdd(&g_counts[bi], 1);
            if (slot < CAP) {
                int base = bi * CAP + slot;
                g_tok[base] = gw;
                g_pairidx[base] = gw * TOPK + k;
                g_score[base] = bvv;
            }
        }
    }
}

// ---------------- scalar outputs ----------------
__global__ void finalize_kernel(float* __restrict__ out) {
    __shared__ float sh[EE];
    int e = threadIdx.x;
    float freq = (float)g_counts[e] / (float)(TOK * TOPK);
    float prob = g_prob_sum[e] * (1.0f / (float)TOK);
    out[OUT_MAIN + 1 + e] = freq;
    out[OUT_MAIN + 1 + EE + e] = prob;
    sh[e] = freq * prob;
    __syncthreads();
    if (e == 0) {
        float s = 0.0f;
        for (int i = 0; i < EE; i++) s += sh[i];
        out[OUT_MAIN] = 0.01f * s;
    }
}

// ---------------- launch ----------------
extern "C" void kernel_launch(void* const* d_in, const int* in_sizes, int n_in,
                              void* d_out, int out_size) {
    const float* x      = (const float*)d_in[0];
    const float* gate_w = (const float*)d_in[1];
    const float* sh1_w  = (const float*)d_in[2];
    const float* sh1_b  = (const float*)d_in[3];
    const float* sh2_w  = (const float*)d_in[4];
    const float* sh2_b  = (const float*)d_in[5];
    const float* e1_w   = (const float*)d_in[6];
    const float* e1_b   = (const float*)d_in[7];
    const float* e2_w   = (const float*)d_in[8];
    const float* e2_b   = (const float*)d_in[9];
    float* out = (float*)d_out;

    int *p_tok, *p_pair;
    __nv_bfloat16 *p_x_hi, *p_x_lo, *p_s1h, *p_s1l, *p_s2h, *p_s2l;
    __nv_bfloat16 *p_e1h, *p_e1l, *p_e2h, *p_e2l;
    __nv_bfloat16 *p_shh_hi, *p_shh_lo, *p_h_hi, *p_h_lo;
    cudaGetSymbolAddress((void**)&p_tok, g_tok);
    cudaGetSymbolAddress((void**)&p_pair, g_pairidx);
    cudaGetSymbolAddress((void**)&p_x_hi, g_x_hi);
    cudaGetSymbolAddress((void**)&p_x_lo, g_x_lo);
    cudaGetSymbolAddress((void**)&p_s1h, g_s1w_hi);
    cudaGetSymbolAddress((void**)&p_s1l, g_s1w_lo);
    cudaGetSymbolAddress((void**)&p_s2h, g_s2w_hi);
    cudaGetSymbolAddress((void**)&p_s2l, g_s2w_lo);
    cudaGetSymbolAddress((void**)&p_e1h, g_e1w_hi);
    cudaGetSymbolAddress((void**)&p_e1l, g_e1w_lo);
    cudaGetSymbolAddress((void**)&p_e2h, g_e2w_hi);
    cudaGetSymbolAddress((void**)&p_e2l, g_e2w_lo);
    cudaGetSymbolAddress((void**)&p_shh_hi, g_shh_hi);
    cudaGetSymbolAddress((void**)&p_shh_lo, g_shh_lo);
    cudaGetSymbolAddress((void**)&p_h_hi, g_h_hi);
    cudaGetSymbolAddress((void**)&p_h_lo, g_h_lo);

    cudaFuncSetAttribute(mgemm<1, 0, 1, 0>,
                         cudaFuncAttributeMaxDynamicSharedMemorySize, TG_SMEM);
    cudaFuncSetAttribute(mgemm<0, 1, 0, 1>,
                         cudaFuncAttributeMaxDynamicSharedMemorySize, TG_SMEM);

    // fused prep (R11-exact)
    prep_kernel<<<PREP_BLKS, 256>>>(x, gate_w, e1_w, sh1_w, e2_w, sh2_w, out);

    topk_route_kernel<<<TOK / 8, 256>>>();
    finalize_kernel<<<1, 64>>>(out);

    // GEMM1: experts (gather tok -> h) + shared (x -> shh)
    mgemm<1, 0, 1, 0><<<dim3(TOK / 128, HH / 128, EE + 1), 128, TG_SMEM>>>(
        p_x_hi, p_x_lo, p_e1h, p_e1l, e1_b, p_tok,
        nullptr, p_h_hi, p_h_lo,
        p_x_hi, p_x_lo, p_s1h, p_s1l, sh1_b,
        nullptr, p_shh_hi, p_shh_lo,
        DD, HH, HH, DD);

    // GEMM2: experts + shared; fused combine via vectorized atomicAdd into out
    mgemm<0, 1, 0, 1><<<dim3(TOK / 128, DD / 128, EE + 1), 128, TG_SMEM>>>(
        p_h_hi, p_h_lo, p_e2h, p_e2l, e2_b, p_pair,
        out, nullptr, nullptr,
        p_shh_hi, p_shh_lo, p_s2h, p_s2l, sh2_b,
        out, nullptr, nullptr,
        HH, DD, DD, HH);
}